// round 4
// baseline (speedup 1.0000x reference)
#include <cuda_runtime.h>
#include <math.h>

#define BB   64
#define TT   256
#define DINN 128
#define UU   1024
#define SEQ  256
#define KSP  8
#define NROW (BB*TT)
#define NB   128        // persistent blocks (<=148 SMs -> co-resident)

// ---------------- device scratch ----------------
__device__ float g_h1[(size_t)NROW * UU];
__device__ float g_x [(size_t)NROW * UU];
__device__ float g_ke[(size_t)NROW * UU];
__device__ float g_h  [BB * UU];
__device__ float g_c  [BB * UU];
__device__ float g_ctx[BB * UU];
__device__ float g_sc [BB * TT];
__device__ float g_qp [(size_t)KSP * BB * 5120];
__device__ float g_zp [(size_t)KSP * BB * 4096];
__device__ unsigned g_bar_cnt = 0;
__device__ unsigned g_bar_gen = 0;

// ---------------- helpers ----------------
__device__ __forceinline__ float tanh_hw(float x) {
    float y; asm("tanh.approx.f32 %0, %1;" : "=f"(y) : "f"(x)); return y;
}
__device__ __forceinline__ float fast_tanh(float x) {   // ~2ulp, for LSTM gates
    float e = __expf(2.0f * x);
    return 1.0f - __fdividef(2.0f, e + 1.0f);
}
__device__ __forceinline__ float sigf(float x) {
    return __fdividef(1.0f, 1.0f + __expf(-x));
}

// software grid barrier: all threads fence, thread0 arrives, spin on gen
__device__ __forceinline__ void grid_bar() {
    __threadfence();
    __syncthreads();
    if (threadIdx.x == 0) {
        unsigned gen = *(volatile unsigned*)&g_bar_gen;
        if (atomicAdd(&g_bar_cnt, 1u) == NB - 1) {
            g_bar_cnt = 0;
            __threadfence();
            atomicAdd(&g_bar_gen, 1u);
        } else {
            while (*(volatile unsigned*)&g_bar_gen == gen) { __nanosleep(64); }
        }
    }
    __syncthreads();
    __threadfence();
}

// ---------------- big precompute SGEMM: C = act(A@B + bias) ----------------
__global__ __launch_bounds__(256, 2)
void sgemm128(const float* __restrict__ A, const float* __restrict__ Bm,
              const float* __restrict__ bias, float* __restrict__ C,
              int M, int N, int K, int doRelu)
{
    __shared__ float As[8][128];
    __shared__ float Bs[8][128];
    const int tid  = threadIdx.x;
    const int brow = blockIdx.y, bcol = blockIdx.x;
    const int tr = tid >> 4, tc = tid & 15;
    const int aRow = tid >> 1, aCol = (tid & 1) * 4;
    const int bRow = tid >> 5, bCol = (tid & 31) * 4;
    const float* Ap = A + (size_t)(brow * 128) * K;
    const float* Bp = Bm + bcol * 128;

    float acc[8][8];
#pragma unroll
    for (int i = 0; i < 8; i++)
#pragma unroll
        for (int j = 0; j < 8; j++) acc[i][j] = 0.f;

    for (int k0 = 0; k0 < K; k0 += 8) {
        float4 av = *(const float4*)(Ap + (size_t)aRow * K + k0 + aCol);
        As[aCol + 0][aRow] = av.x; As[aCol + 1][aRow] = av.y;
        As[aCol + 2][aRow] = av.z; As[aCol + 3][aRow] = av.w;
        float4 bv = *(const float4*)(Bp + (size_t)(k0 + bRow) * N + bCol);
        *(float4*)&Bs[bRow][bCol] = bv;
        __syncthreads();
#pragma unroll
        for (int kk = 0; kk < 8; kk++) {
            float4 a0 = *(const float4*)&As[kk][tr * 8];
            float4 a1 = *(const float4*)&As[kk][tr * 8 + 4];
            float4 b0 = *(const float4*)&Bs[kk][tc * 8];
            float4 b1 = *(const float4*)&Bs[kk][tc * 8 + 4];
            float ar[8] = {a0.x,a0.y,a0.z,a0.w,a1.x,a1.y,a1.z,a1.w};
            float br[8] = {b0.x,b0.y,b0.z,b0.w,b1.x,b1.y,b1.z,b1.w};
#pragma unroll
            for (int i = 0; i < 8; i++)
#pragma unroll
                for (int j = 0; j < 8; j++)
                    acc[i][j] = fmaf(ar[i], br[j], acc[i][j]);
        }
        __syncthreads();
    }
#pragma unroll
    for (int i = 0; i < 8; i++) {
        int row = brow * 128 + tr * 8 + i;
#pragma unroll
        for (int j = 0; j < 8; j++) {
            int col = bcol * 128 + tc * 8 + j;
            float v = acc[i][j] + bias[col];
            if (doRelu) v = fmaxf(v, 0.f);
            C[(size_t)row * N + col] = v;
        }
    }
}

// ---------------- init: zero h, c, out ----------------
__global__ void init_state(float* __restrict__ out)
{
    int idx = blockIdx.x * blockDim.x + threadIdx.x;
    if (idx < BB * UU) { g_h[idx] = 0.f; g_c[idx] = 0.f; }
    if (idx < SEQ * BB) out[idx] = 0.f;
}

// ---------------- GEMM tile inside persistent kernel ----------------
// BM=64, BN=64, K-slice=128 (split-K), 256 threads, TM=TN=4
__device__ __forceinline__ void gemm_tile(const float* __restrict__ A,
                                          const float* __restrict__ Bp, int ldb,
                                          float* __restrict__ Cp, int ldc,
                                          int kbase, float* sm)
{
    float* As = sm;          // [16][64] transposed (k-major)
    float* Bs = sm + 1024;   // [16][64]
    const int tid = threadIdx.x;
    const int tr = tid >> 4;     // 0..15 -> rows tr*4
    const int tc = tid & 15;     // 0..15 -> cols tc*4
    const int ar = tid >> 2;           // 0..63  A row
    const int ac = (tid & 3) * 4;      // 0,4,8,12
    const int br = tid >> 4;           // 0..15  B row
    const int bc = (tid & 15) * 4;     // 0..60

    float acc[4][4];
#pragma unroll
    for (int i = 0; i < 4; i++)
#pragma unroll
        for (int j = 0; j < 4; j++) acc[i][j] = 0.f;

    for (int kb = 0; kb < 128; kb += 16) {
        const int k0 = kbase + kb;
        float4 av = *(const float4*)(A + (size_t)ar * UU + k0 + ac);
        As[(ac + 0) * 64 + ar] = av.x; As[(ac + 1) * 64 + ar] = av.y;
        As[(ac + 2) * 64 + ar] = av.z; As[(ac + 3) * 64 + ar] = av.w;
        *(float4*)&Bs[br * 64 + bc] = *(const float4*)(Bp + (size_t)(k0 + br) * ldb + bc);
        __syncthreads();
#pragma unroll
        for (int kk = 0; kk < 16; kk++) {
            float4 a4 = *(const float4*)&As[kk * 64 + tr * 4];
            float4 b4 = *(const float4*)&Bs[kk * 64 + tc * 4];
            float arr[4] = {a4.x, a4.y, a4.z, a4.w};
            float brr[4] = {b4.x, b4.y, b4.z, b4.w};
#pragma unroll
            for (int i = 0; i < 4; i++)
#pragma unroll
                for (int j = 0; j < 4; j++)
                    acc[i][j] = fmaf(arr[i], brr[j], acc[i][j]);
        }
        __syncthreads();
    }
#pragma unroll
    for (int i = 0; i < 4; i++) {
        float* cr = Cp + (size_t)(tr * 4 + i) * ldc + tc * 4;
        cr[0] = acc[i][0]; cr[1] = acc[i][1]; cr[2] = acc[i][2]; cr[3] = acc[i][3];
    }
    __syncthreads();
}

// ---------------- persistent decode kernel ----------------
__global__ __launch_bounds__(256, 1)
void decode_persistent(const float* __restrict__ W1, const float* __restrict__ b1,
                       const float* __restrict__ V,
                       const float* __restrict__ Wk, const float* __restrict__ Wr,
                       const float* __restrict__ bl, const float* __restrict__ Wo,
                       const float* __restrict__ bo, float* __restrict__ out)
{
    __shared__ float sm[2048];
    __shared__ float red[8];
    const int tid  = threadIdx.x;
    const int bid  = blockIdx.x;
    const int warp = tid >> 5, lane = tid & 31;
    const int b2   = bid >> 1;      // batch for paired phases
    const int half = bid & 1;

    for (int s = 0; s < SEQ; s++) {
        // ---- phase 1: q|hr partials = h @ [W1|Wr], split-K=8, N=5120 ----
        for (int u = bid; u < 80 * KSP; u += NB) {
            const int nt = u % 80, ks = u / 80;
            const int n0 = nt * 64;
            const float* Bp; int ldb;
            if (n0 < 1024) { Bp = W1 + n0; ldb = 1024; }
            else           { Bp = Wr + (n0 - 1024); ldb = 4096; }
            gemm_tile(g_h, Bp, ldb,
                      g_qp + (size_t)ks * BB * 5120 + n0, 5120, ks * 128, sm);
        }
        grid_bar();

        // ---- phase 2: attention scores (block = (batch, t-half)) ----
        {
            float* qs = sm;          // [1024]
            float* vs = sm + 1024;   // [1024]
            for (int u = tid; u < 1024; u += 256) {
                float q = b1[u];
#pragma unroll
                for (int ks = 0; ks < KSP; ks++)
                    q += g_qp[(size_t)ks * BB * 5120 + (size_t)b2 * 5120 + u];
                qs[u] = q;
                vs[u] = V[u];
            }
            __syncthreads();
            for (int t = warp; t < 128; t += 8) {
                const int tt = half * 128 + t;
                const float* kp = g_ke + ((size_t)(b2 * 256 + tt)) * 1024;
                float s0 = 0.f;
                for (int u0 = lane * 4; u0 < 1024; u0 += 128) {
                    float4 k4 = *(const float4*)(kp + u0);
                    float4 q4 = *(const float4*)(qs + u0);
                    float4 v4 = *(const float4*)(vs + u0);
                    s0 += v4.x * tanh_hw(q4.x + k4.x);
                    s0 += v4.y * tanh_hw(q4.y + k4.y);
                    s0 += v4.z * tanh_hw(q4.z + k4.z);
                    s0 += v4.w * tanh_hw(q4.w + k4.w);
                }
#pragma unroll
                for (int o = 16; o; o >>= 1) s0 += __shfl_xor_sync(0xffffffffu, s0, o);
                if (!lane) g_sc[b2 * 256 + tt] = s0;
            }
        }
        grid_bar();

        // ---- phase 3: softmax (redundant per block) + ctx (block = (batch, u-half)) ----
        {
            float v = g_sc[b2 * 256 + tid];
            float m = v;
#pragma unroll
            for (int o = 16; o; o >>= 1) m = fmaxf(m, __shfl_xor_sync(0xffffffffu, m, o));
            if (!lane) red[warp] = m;
            __syncthreads();
            float bm = red[0];
#pragma unroll
            for (int w = 1; w < 8; w++) bm = fmaxf(bm, red[w]);
            __syncthreads();
            float e = __expf(v - bm);
            float ss = e;
#pragma unroll
            for (int o = 16; o; o >>= 1) ss += __shfl_xor_sync(0xffffffffu, ss, o);
            if (!lane) red[warp] = ss;
            __syncthreads();
            float bs = 0.f;
#pragma unroll
            for (int w = 0; w < 8; w++) bs += red[w];
            sm[tid] = __fdividef(e, bs);
            __syncthreads();

            const int u2 = half * 512 + tid * 2;
            const float* xb = g_x + (size_t)b2 * 256 * 1024 + u2;
            float ax = 0.f, ay = 0.f;
#pragma unroll 4
            for (int t = 0; t < 256; t++) {
                float2 xv = *(const float2*)(xb + (size_t)t * 1024);
                float wt = sm[t];
                ax = fmaf(wt, xv.x, ax);
                ay = fmaf(wt, xv.y, ay);
            }
            *(float2*)(g_ctx + b2 * 1024 + u2) = make_float2(ax, ay);
            __syncthreads();
        }
        grid_bar();

        // ---- phase 4: zp partials = ctx @ Wk, split-K=8, N=4096 ----
        for (int u = bid; u < 64 * KSP; u += NB) {
            const int nt = u & 63, ks = u >> 6;
            const int n0 = nt * 64;
            gemm_tile(g_ctx, Wk + n0, 4096,
                      g_zp + (size_t)ks * BB * 4096 + n0, 4096, ks * 128, sm);
        }
        grid_bar();

        // ---- phase 5: LSTM gates + state + projection (block = (batch, j-half)) ----
        {
            const int j0 = half * 512 + tid * 2;
            float2 zi = {bl[j0], bl[j0+1]};
            float2 zf = {bl[1024+j0], bl[1024+j0+1]};
            float2 zg = {bl[2048+j0], bl[2048+j0+1]};
            float2 zo = {bl[3072+j0], bl[3072+j0+1]};
#pragma unroll
            for (int ks = 0; ks < KSP; ks++) {
                const float* zp = g_zp + (size_t)ks * BB * 4096 + (size_t)b2 * 4096;
                const float* hp = g_qp + (size_t)ks * BB * 5120 + (size_t)b2 * 5120 + 1024;
                float2 a, c;
                a = *(const float2*)(zp + j0);        c = *(const float2*)(hp + j0);
                zi.x += a.x + c.x; zi.y += a.y + c.y;
                a = *(const float2*)(zp + 1024 + j0); c = *(const float2*)(hp + 1024 + j0);
                zf.x += a.x + c.x; zf.y += a.y + c.y;
                a = *(const float2*)(zp + 2048 + j0); c = *(const float2*)(hp + 2048 + j0);
                zg.x += a.x + c.x; zg.y += a.y + c.y;
                a = *(const float2*)(zp + 3072 + j0); c = *(const float2*)(hp + 3072 + j0);
                zo.x += a.x + c.x; zo.y += a.y + c.y;
            }
            float2 cold = *(const float2*)(g_c + b2 * 1024 + j0);
            float cx = sigf(zf.x) * cold.x + sigf(zi.x) * fast_tanh(zg.x);
            float cy = sigf(zf.y) * cold.y + sigf(zi.y) * fast_tanh(zg.y);
            float hx = sigf(zo.x) * fast_tanh(cx);
            float hy = sigf(zo.y) * fast_tanh(cy);
            *(float2*)(g_c + b2 * 1024 + j0) = make_float2(cx, cy);
            *(float2*)(g_h + b2 * 1024 + j0) = make_float2(hx, hy);

            float p = hx * Wo[j0] + hy * Wo[j0 + 1];
            if (tid == 0 && half == 0) p += bo[0];
#pragma unroll
            for (int o = 16; o; o >>= 1) p += __shfl_xor_sync(0xffffffffu, p, o);
            if (!lane) red[warp] = p;
            __syncthreads();
            if (tid == 0) {
                float acc = 0.f;
#pragma unroll
                for (int w = 0; w < 8; w++) acc += red[w];
                atomicAdd(&out[s * 64 + b2], acc);
            }
            __syncthreads();
        }
        grid_bar();
    }
}

// ---------------- host launcher ----------------
extern "C" void kernel_launch(void* const* d_in, const int* in_sizes, int n_in,
                              void* d_out, int out_size)
{
    const float* inputs = (const float*)d_in[0];
    const float* We1 = (const float*)d_in[1];  const float* be1 = (const float*)d_in[2];
    const float* We2 = (const float*)d_in[3];  const float* be2 = (const float*)d_in[4];
    const float* W1  = (const float*)d_in[5];  const float* b1  = (const float*)d_in[6];
    const float* W2  = (const float*)d_in[7];  const float* b2  = (const float*)d_in[8];
    const float* V   = (const float*)d_in[9];  /* bV (d_in[10]) shift-invariant in softmax */
    const float* Wk  = (const float*)d_in[11]; const float* Wr  = (const float*)d_in[12];
    const float* bl  = (const float*)d_in[13]; const float* Wo  = (const float*)d_in[14];
    const float* bo  = (const float*)d_in[15];
    float* out = (float*)d_out;

    float *p_h1, *p_x, *p_ke;
    cudaGetSymbolAddress((void**)&p_h1, g_h1);
    cudaGetSymbolAddress((void**)&p_x,  g_x);
    cudaGetSymbolAddress((void**)&p_ke, g_ke);

    dim3 gpre(UU / 128, NROW / 128);
    sgemm128<<<gpre, 256>>>(inputs, We1, be1, p_h1, NROW, UU, DINN, 1);
    sgemm128<<<gpre, 256>>>(p_h1,   We2, be2, p_x,  NROW, UU, UU,   1);
    sgemm128<<<gpre, 256>>>(p_x,    W2,  b2,  p_ke, NROW, UU, UU,   0);
    init_state<<<64, 1024>>>(out);
    decode_persistent<<<NB, 256>>>(W1, b1, V, Wk, Wr, bl, Wo, bo, out);
}

// round 6
// speedup vs baseline: 1.4880x; 1.4880x over previous
#include <cuda_runtime.h>
#include <cuda_bf16.h>
#include <math.h>

#define BB   64
#define TT   256
#define DINN 128
#define UU   1024
#define SEQ  256
#define NROW (BB*TT)
#define NB   128
#define N1   5120       // [W1 | Wr]
#define N2   4096       // Wk

// ---------------- device scratch ----------------
__device__ float g_h1[(size_t)NROW * UU];
__device__ float g_x [(size_t)NROW * UU];
__device__ float g_ke[(size_t)NROW * UU];
// split bf16 (hi,lo) packed fragments
__device__ __nv_bfloat16 g_Wpk1[(size_t)UU * N1 * 2];  // B-frags [W1|Wr]
__device__ __nv_bfloat16 g_Wpk2[(size_t)UU * N2 * 2];  // B-frags Wk
__device__ __nv_bfloat16 g_hpk[BB * UU * 2];           // A-frags h (hi+lo)
__device__ __nv_bfloat16 g_cpk[BB * UU * 2];           // A-frags ctx (hi+lo)
__device__ float g_q [BB * N1];
__device__ float g_z [BB * N2];
__device__ float g_c [BB * UU];
__device__ float g_sc[BB * TT];
__device__ unsigned g_bar_cnt = 0;
__device__ unsigned g_bar_gen = 0;

// ---------------- helpers ----------------
__device__ __forceinline__ float tanh_hw(float x) {
    float y; asm("tanh.approx.f32 %0, %1;" : "=f"(y) : "f"(x)); return y;
}
__device__ __forceinline__ float fast_tanh(float x) {
    float e = __expf(2.0f * x);
    return 1.0f - __fdividef(2.0f, e + 1.0f);
}
__device__ __forceinline__ float sigf(float x) {
    return __fdividef(1.0f, 1.0f + __expf(-x));
}

__device__ __forceinline__ void mma16816(float d[4], const uint4& a, const uint2& b) {
    asm("mma.sync.aligned.m16n8k16.row.col.f32.bf16.bf16.f32 "
        "{%0,%1,%2,%3},{%4,%5,%6,%7},{%8,%9},{%0,%1,%2,%3};"
        : "+f"(d[0]), "+f"(d[1]), "+f"(d[2]), "+f"(d[3])
        : "r"(a.x), "r"(a.y), "r"(a.z), "r"(a.w), "r"(b.x), "r"(b.y));
}

__device__ __forceinline__ void grid_bar() {
    __threadfence();
    __syncthreads();
    if (threadIdx.x == 0) {
        unsigned gen = *(volatile unsigned*)&g_bar_gen;
        if (atomicAdd(&g_bar_cnt, 1u) == NB - 1) {
            g_bar_cnt = 0;
            __threadfence();
            atomicAdd(&g_bar_gen, 1u);
        } else {
            while (*(volatile unsigned*)&g_bar_gen == gen) { }
        }
    }
    __syncthreads();
    __threadfence();
}

// ---------------- precompute SGEMM (fp32): C = act(A@B + bias) ----------------
__global__ __launch_bounds__(256, 2)
void sgemm128(const float* __restrict__ A, const float* __restrict__ Bm,
              const float* __restrict__ bias, float* __restrict__ C,
              int M, int N, int K, int doRelu)
{
    __shared__ float As[8][128];
    __shared__ float Bs[8][128];
    const int tid  = threadIdx.x;
    const int brow = blockIdx.y, bcol = blockIdx.x;
    const int tr = tid >> 4, tc = tid & 15;
    const int aRow = tid >> 1, aCol = (tid & 1) * 4;
    const int bRow = tid >> 5, bCol = (tid & 31) * 4;
    const float* Ap = A + (size_t)(brow * 128) * K;
    const float* Bp = Bm + bcol * 128;

    float acc[8][8];
#pragma unroll
    for (int i = 0; i < 8; i++)
#pragma unroll
        for (int j = 0; j < 8; j++) acc[i][j] = 0.f;

    for (int k0 = 0; k0 < K; k0 += 8) {
        float4 av = *(const float4*)(Ap + (size_t)aRow * K + k0 + aCol);
        As[aCol + 0][aRow] = av.x; As[aCol + 1][aRow] = av.y;
        As[aCol + 2][aRow] = av.z; As[aCol + 3][aRow] = av.w;
        float4 bv = *(const float4*)(Bp + (size_t)(k0 + bRow) * N + bCol);
        *(float4*)&Bs[bRow][bCol] = bv;
        __syncthreads();
#pragma unroll
        for (int kk = 0; kk < 8; kk++) {
            float4 a0 = *(const float4*)&As[kk][tr * 8];
            float4 a1 = *(const float4*)&As[kk][tr * 8 + 4];
            float4 b0 = *(const float4*)&Bs[kk][tc * 8];
            float4 b1 = *(const float4*)&Bs[kk][tc * 8 + 4];
            float ar[8] = {a0.x,a0.y,a0.z,a0.w,a1.x,a1.y,a1.z,a1.w};
            float br[8] = {b0.x,b0.y,b0.z,b0.w,b1.x,b1.y,b1.z,b1.w};
#pragma unroll
            for (int i = 0; i < 8; i++)
#pragma unroll
                for (int j = 0; j < 8; j++)
                    acc[i][j] = fmaf(ar[i], br[j], acc[i][j]);
        }
        __syncthreads();
    }
#pragma unroll
    for (int i = 0; i < 8; i++) {
        int row = brow * 128 + tr * 8 + i;
#pragma unroll
        for (int j = 0; j < 8; j++) {
            int col = bcol * 128 + tc * 8 + j;
            float v = acc[i][j] + bias[col];
            if (doRelu) v = fmaxf(v, 0.f);
            C[(size_t)row * N + col] = v;
        }
    }
}

// ---------------- split helper ----------------
__device__ __forceinline__ void split_bf16(float v, __nv_bfloat16& hi, __nv_bfloat16& lo) {
    hi = __float2bfloat16(v);
    lo = __float2bfloat16(v - __bfloat162float(hi));
}

// ---------------- pack weights into split B-fragment layout ----------------
// entry e=(nt8*64+kt)*32+l holds 8 bf16: {hi0,hi1,hi2,hi3, lo0,lo1,lo2,lo3}
//   el0,el1 = W[kt*16+(l&3)*2 + {0,1}][nt8*8 + l/4]
//   el2,el3 = W[kt*16+(l&3)*2+8 + {0,1}][same n]
__global__ void pack_weights(const float* __restrict__ W1, const float* __restrict__ Wr,
                             const float* __restrict__ Wk)
{
    const int TOT1 = (N1 / 8) * 64 * 32;
    const int TOT2 = (N2 / 8) * 64 * 32;
    int c = blockIdx.x * blockDim.x + threadIdx.x;
    float w[4];
    __nv_bfloat16* o;
    if (c < TOT1) {
        int nt = c / 2048, rem = c % 2048, kt = rem >> 5, l = rem & 31;
        int n  = nt * 8 + (l >> 2);
        int k0 = kt * 16 + (l & 3) * 2;
        const float* W; int ld, nn;
        if (n < 1024) { W = W1; ld = 1024; nn = n; }
        else          { W = Wr; ld = 4096; nn = n - 1024; }
        w[0] = W[(size_t)(k0    ) * ld + nn];
        w[1] = W[(size_t)(k0 + 1) * ld + nn];
        w[2] = W[(size_t)(k0 + 8) * ld + nn];
        w[3] = W[(size_t)(k0 + 9) * ld + nn];
        o = g_Wpk1 + (size_t)c * 8;
    } else if (c < TOT1 + TOT2) {
        int c2 = c - TOT1;
        int nt = c2 / 2048, rem = c2 % 2048, kt = rem >> 5, l = rem & 31;
        int n  = nt * 8 + (l >> 2);
        int k0 = kt * 16 + (l & 3) * 2;
        w[0] = Wk[(size_t)(k0    ) * 4096 + n];
        w[1] = Wk[(size_t)(k0 + 1) * 4096 + n];
        w[2] = Wk[(size_t)(k0 + 8) * 4096 + n];
        w[3] = Wk[(size_t)(k0 + 9) * 4096 + n];
        o = g_Wpk2 + (size_t)c2 * 8;
    } else return;
#pragma unroll
    for (int i = 0; i < 4; i++) split_bf16(w[i], o[i], o[4 + i]);
}

// ---------------- init ----------------
__global__ void init_state(float* __restrict__ out)
{
    int idx = blockIdx.x * blockDim.x + threadIdx.x;
    if (idx < BB * UU) {
        g_c[idx] = 0.f;
        g_hpk[idx] = __float2bfloat16(0.f);
        g_hpk[BB * UU + idx] = __float2bfloat16(0.f);
    }
    if (idx < SEQ * BB) out[idx] = 0.f;
}

// ---------------- split-bf16 HMMA GEMM: C[64,N] = A(64x1024) @ W(1024xN) ----
// A entries: 16 bf16 per (lane, kt): hi uint4 then lo uint4.
// block-tile 64x32, warp=(mt,np): m16 x n16 (two n8 frags), K=1024
__device__ __forceinline__ void hgemm_phase(const __nv_bfloat16* __restrict__ Apk,
                                            const __nv_bfloat16* __restrict__ Wpk,
                                            const float* __restrict__ bias,
                                            float* __restrict__ C,
                                            int ntiles, int ldc)
{
    const int tid = threadIdx.x;
    const int w = tid >> 5, l = tid & 31;
    const int mt = w >> 1, np = w & 1;
    const uint4* ap = (const uint4*)Apk;   // 2 uint4 per entry (hi, lo)
    const uint4* bp = (const uint4*)Wpk;   // 1 uint4 per entry {hi.xy, lo.zw}

    for (int bt = blockIdx.x; bt < ntiles; bt += NB) {
        const int n0  = bt * 32;
        const int nt0 = (n0 >> 3) + np * 2;
        float d0[4] = {0.f,0.f,0.f,0.f};
        float d1[4] = {0.f,0.f,0.f,0.f};
        const uint4* a_it  = ap + (mt * 64 * 32 + l) * 2;
        const uint4* b0_it = bp + nt0 * 64 * 32 + l;
        const uint4* b1_it = bp + (nt0 + 1) * 64 * 32 + l;
#pragma unroll 4
        for (int kt = 0; kt < 64; kt++) {
            uint4 aH = a_it[kt * 64];
            uint4 aL = a_it[kt * 64 + 1];
            uint4 b0 = b0_it[kt * 32];
            uint4 b1 = b1_it[kt * 32];
            uint2 b0H = make_uint2(b0.x, b0.y), b0L = make_uint2(b0.z, b0.w);
            uint2 b1H = make_uint2(b1.x, b1.y), b1L = make_uint2(b1.z, b1.w);
            mma16816(d0, aH, b0H);
            mma16816(d0, aH, b0L);
            mma16816(d0, aL, b0H);
            mma16816(d1, aH, b1H);
            mma16816(d1, aH, b1L);
            mma16816(d1, aL, b1H);
        }
        const int r0 = mt * 16 + (l >> 2);
        const int c0 = n0 + np * 16 + ((l & 3) << 1);
        if (bias && n0 < 1024) {   // bias valid only on first 1024 cols
            float2 bbA = *(const float2*)&bias[c0];
            float2 bbB = *(const float2*)&bias[c0 + 8];
            d0[0] += bbA.x; d0[1] += bbA.y; d0[2] += bbA.x; d0[3] += bbA.y;
            d1[0] += bbB.x; d1[1] += bbB.y; d1[2] += bbB.x; d1[3] += bbB.y;
        }
        *(float2*)&C[(size_t)r0 * ldc + c0]           = make_float2(d0[0], d0[1]);
        *(float2*)&C[(size_t)(r0 + 8) * ldc + c0]     = make_float2(d0[2], d0[3]);
        *(float2*)&C[(size_t)r0 * ldc + c0 + 8]       = make_float2(d1[0], d1[1]);
        *(float2*)&C[(size_t)(r0 + 8) * ldc + c0 + 8] = make_float2(d1[2], d1[3]);
    }
}

// ---------------- pack one fp32 pair into split A-fragment layout ----------------
__device__ __forceinline__ void pack_a(__nv_bfloat16* dst, int row, int u,
                                       float vx, float vy)
{
    const int mt = row >> 4, rm = row & 15;
    const int kt = u >> 4,  cm = u & 15;          // u even
    const int lane = (rm & 7) * 4 + ((cm & 7) >> 1);
    const int reg  = (rm >> 3) + ((cm >> 3) & 1) * 2;
    const int base = ((mt * 64 + kt) * 32 + lane) * 16;
    __nv_bfloat16 hx, lx, hy, ly;
    split_bf16(vx, hx, lx);
    split_bf16(vy, hy, ly);
    __nv_bfloat162 hp; hp.x = hx; hp.y = hy;
    __nv_bfloat162 lp; lp.x = lx; lp.y = ly;
    *(__nv_bfloat162*)&dst[base + reg * 2]     = hp;
    *(__nv_bfloat162*)&dst[base + 8 + reg * 2] = lp;
}

// ---------------- persistent decode ----------------
__global__ __launch_bounds__(256, 1)
void decode_persistent(const float* __restrict__ b1, const float* __restrict__ V,
                       const float* __restrict__ bl, const float* __restrict__ Wo,
                       const float* __restrict__ bo, float* __restrict__ out)
{
    __shared__ float sm[256];
    __shared__ float red[8];
    const int tid  = threadIdx.x;
    const int bid  = blockIdx.x;
    const int warp = tid >> 5, lane = tid & 31;
    const int b2   = bid >> 1;
    const int half = bid & 1;

    // V slice in registers: vr[it*4+j] = V[it*128 + lane*4 + j]
    float vr[32];
#pragma unroll
    for (int it = 0; it < 8; it++) {
        float4 a = *(const float4*)&V[it * 128 + lane * 4];
        vr[it*4+0]=a.x; vr[it*4+1]=a.y; vr[it*4+2]=a.z; vr[it*4+3]=a.w;
    }

    for (int s = 0; s < SEQ; s++) {
        // ---- phase 1: g_q = h @ [W1|Wr] (+b1 on cols<1024) ----
        hgemm_phase(g_hpk, g_Wpk1, b1, g_q, N1 / 32, N1);
        grid_bar();

        // ---- phase 2: attention scores for (b2, half), fp32 keys ----
        {
            float qr[32];
#pragma unroll
            for (int it = 0; it < 8; it++) {
                float4 a = *(const float4*)&g_q[b2 * N1 + it * 128 + lane * 4];
                qr[it*4+0]=a.x; qr[it*4+1]=a.y; qr[it*4+2]=a.z; qr[it*4+3]=a.w;
            }
            for (int t = warp; t < 128; t += 8) {
                const int tt = half * 128 + t;
                const float4* kp = (const float4*)(g_ke + ((size_t)(b2 * 256 + tt)) * 1024);
                float s0 = 0.f;
#pragma unroll
                for (int it = 0; it < 8; it++) {
                    float4 kv = kp[it * 32 + lane];
                    s0 += vr[it*4+0] * tanh_hw(qr[it*4+0] + kv.x);
                    s0 += vr[it*4+1] * tanh_hw(qr[it*4+1] + kv.y);
                    s0 += vr[it*4+2] * tanh_hw(qr[it*4+2] + kv.z);
                    s0 += vr[it*4+3] * tanh_hw(qr[it*4+3] + kv.w);
                }
#pragma unroll
                for (int o = 16; o; o >>= 1) s0 += __shfl_xor_sync(0xffffffffu, s0, o);
                if (!lane) g_sc[b2 * 256 + tt] = s0;
            }
        }
        grid_bar();

        // ---- phase 3: softmax + ctx (fp32 x), pack ctx split A-frags ----
        {
            float v = g_sc[b2 * 256 + tid];
            float m = v;
#pragma unroll
            for (int o = 16; o; o >>= 1) m = fmaxf(m, __shfl_xor_sync(0xffffffffu, m, o));
            if (!lane) red[warp] = m;
            __syncthreads();
            float bm = red[0];
#pragma unroll
            for (int w = 1; w < 8; w++) bm = fmaxf(bm, red[w]);
            __syncthreads();
            float e = __expf(v - bm);
            float ss = e;
#pragma unroll
            for (int o = 16; o; o >>= 1) ss += __shfl_xor_sync(0xffffffffu, ss, o);
            if (!lane) red[warp] = ss;
            __syncthreads();
            float bs = 0.f;
#pragma unroll
            for (int w = 0; w < 8; w++) bs += red[w];
            sm[tid] = __fdividef(e, bs);
            __syncthreads();

            const int u2 = half * 512 + tid * 2;
            const float* xb = g_x + (size_t)b2 * 256 * 1024 + u2;
            float ax = 0.f, ay = 0.f;
#pragma unroll 4
            for (int t = 0; t < 256; t++) {
                float2 xv = *(const float2*)(xb + (size_t)t * 1024);
                float wt = sm[t];
                ax = fmaf(wt, xv.x, ax);
                ay = fmaf(wt, xv.y, ay);
            }
            pack_a(g_cpk, b2, u2, ax, ay);
            __syncthreads();
        }
        grid_bar();

        // ---- phase 4: g_z = ctx @ Wk ----
        hgemm_phase(g_cpk, g_Wpk2, (const float*)0, g_z, N2 / 32, N2);
        grid_bar();

        // ---- phase 5: LSTM gates + state + projection; pack new h ----
        {
            const int j0 = half * 512 + tid * 2;
            const float* zb = g_z + (size_t)b2 * N2;
            const float* hb = g_q + (size_t)b2 * N1 + 1024;
            float2 a, b;
            a = *(const float2*)&zb[j0];        b = *(const float2*)&hb[j0];
            float2 zi = { bl[j0]   + a.x + b.x, bl[j0+1]   + a.y + b.y };
            a = *(const float2*)&zb[1024+j0];   b = *(const float2*)&hb[1024+j0];
            float2 zf = { bl[1024+j0] + a.x + b.x, bl[1024+j0+1] + a.y + b.y };
            a = *(const float2*)&zb[2048+j0];   b = *(const float2*)&hb[2048+j0];
            float2 zg = { bl[2048+j0] + a.x + b.x, bl[2048+j0+1] + a.y + b.y };
            a = *(const float2*)&zb[3072+j0];   b = *(const float2*)&hb[3072+j0];
            float2 zo = { bl[3072+j0] + a.x + b.x, bl[3072+j0+1] + a.y + b.y };

            float2 cold = *(const float2*)&g_c[b2 * 1024 + j0];
            float cx = sigf(zf.x) * cold.x + sigf(zi.x) * fast_tanh(zg.x);
            float cy = sigf(zf.y) * cold.y + sigf(zi.y) * fast_tanh(zg.y);
            float hx = sigf(zo.x) * fast_tanh(cx);
            float hy = sigf(zo.y) * fast_tanh(cy);
            *(float2*)&g_c[b2 * 1024 + j0] = make_float2(cx, cy);
            pack_a(g_hpk, b2, j0, hx, hy);

            float p = hx * Wo[j0] + hy * Wo[j0 + 1];
            if (tid == 0 && half == 0) p += bo[0];
#pragma unroll
            for (int o = 16; o; o >>= 1) p += __shfl_xor_sync(0xffffffffu, p, o);
            if (!lane) red[warp] = p;
            __syncthreads();
            if (tid == 0) {
                float acc = 0.f;
#pragma unroll
                for (int w = 0; w < 8; w++) acc += red[w];
                atomicAdd(&out[s * 64 + b2], acc);
            }
            __syncthreads();
        }
        grid_bar();
    }
}

// ---------------- host launcher ----------------
extern "C" void kernel_launch(void* const* d_in, const int* in_sizes, int n_in,
                              void* d_out, int out_size)
{
    const float* inputs = (const float*)d_in[0];
    const float* We1 = (const float*)d_in[1];  const float* be1 = (const float*)d_in[2];
    const float* We2 = (const float*)d_in[3];  const float* be2 = (const float*)d_in[4];
    const float* W1  = (const float*)d_in[5];  const float* b1  = (const float*)d_in[6];
    const float* W2  = (const float*)d_in[7];  const float* b2  = (const float*)d_in[8];
    const float* V   = (const float*)d_in[9];  /* bV shift-invariant in softmax */
    const float* Wk  = (const float*)d_in[11]; const float* Wr  = (const float*)d_in[12];
    const float* bl  = (const float*)d_in[13]; const float* Wo  = (const float*)d_in[14];
    const float* bo  = (const float*)d_in[15];
    float* out = (float*)d_out;

    float *p_h1, *p_x, *p_ke;
    cudaGetSymbolAddress((void**)&p_h1, g_h1);
    cudaGetSymbolAddress((void**)&p_x,  g_x);
    cudaGetSymbolAddress((void**)&p_ke, g_ke);

    dim3 gpre(UU / 128, NROW / 128);
    sgemm128<<<gpre, 256>>>(inputs, We1, be1, p_h1, NROW, UU, DINN, 1);
    sgemm128<<<gpre, 256>>>(p_h1,   We2, be2, p_x,  NROW, UU, UU,   1);
    sgemm128<<<gpre, 256>>>(p_x,    W2,  b2,  p_ke, NROW, UU, UU,   0);
    pack_weights<<<4608, 512>>>(W1, Wr, Wk);
    init_state<<<64, 1024>>>(out);
    decode_persistent<<<NB, 256>>>(b1, V, bl, Wo, bo, out);
}

// round 7
// speedup vs baseline: 1.6246x; 1.0919x over previous
#include <cuda_runtime.h>
#include <cuda_bf16.h>
#include <cuda_fp16.h>
#include <math.h>

#define BB   64
#define TT   256
#define DINN 128
#define UU   1024
#define SEQ  256
#define NROW (BB*TT)
#define NB   128
#define N1   5120       // [W1 | Wr]
#define N2   4096       // Wk

// ---------------- device scratch ----------------
// split-bf16 packed fragment buffers (hi+lo)
__device__ __nv_bfloat16 g_h1pk[(size_t)NROW * UU * 2];   // h1 A-frags
__device__ __nv_bfloat16 g_xpk [(size_t)NROW * UU * 2];   // x  A-frags
__device__ __half g_xh [(size_t)NROW * UU];               // x  fp16 linear
__device__ __half g_keh[(size_t)NROW * UU];               // keys fp16 linear
__device__ __nv_bfloat16 g_Wpk1 [(size_t)UU * N1 * 2];    // B-frags [W1|Wr]
__device__ __nv_bfloat16 g_Wpk2 [(size_t)UU * N2 * 2];    // B-frags Wk
__device__ __nv_bfloat16 g_We2pk[(size_t)UU * UU * 2];    // B-frags We2
__device__ __nv_bfloat16 g_W2pk [(size_t)UU * UU * 2];    // B-frags W2
__device__ __nv_bfloat16 g_hpk[BB * UU * 2];              // A-frags h (hi+lo)
__device__ __nv_bfloat16 g_cpk[BB * UU * 2];              // A-frags ctx
__device__ float g_q [BB * N1];
__device__ float g_z [BB * N2];
__device__ float g_c [BB * UU];
__device__ float g_sc[BB * TT];
__device__ unsigned g_bar_cnt = 0;
__device__ unsigned g_bar_gen = 0;

// ---------------- helpers ----------------
__device__ __forceinline__ float tanh_hw(float x) {
    float y; asm("tanh.approx.f32 %0, %1;" : "=f"(y) : "f"(x)); return y;
}
__device__ __forceinline__ float fast_tanh(float x) {
    float e = __expf(2.0f * x);
    return 1.0f - __fdividef(2.0f, e + 1.0f);
}
__device__ __forceinline__ float sigf(float x) {
    return __fdividef(1.0f, 1.0f + __expf(-x));
}

__device__ __forceinline__ void mma16816(float d[4], const uint4& a, const uint2& b) {
    asm("mma.sync.aligned.m16n8k16.row.col.f32.bf16.bf16.f32 "
        "{%0,%1,%2,%3},{%4,%5,%6,%7},{%8,%9},{%0,%1,%2,%3};"
        : "+f"(d[0]), "+f"(d[1]), "+f"(d[2]), "+f"(d[3])
        : "r"(a.x), "r"(a.y), "r"(a.z), "r"(a.w), "r"(b.x), "r"(b.y));
}

// lightweight grid barrier: release-arrive / acquire-spin, thread0 only
__device__ __forceinline__ void grid_bar() {
    __syncthreads();
    if (threadIdx.x == 0) {
        unsigned gen;
        asm volatile("ld.acquire.gpu.u32 %0, [%1];" : "=r"(gen) : "l"(&g_bar_gen));
        unsigned prev;
        asm volatile("atom.add.release.gpu.u32 %0, [%1], 1;"
                     : "=r"(prev) : "l"(&g_bar_cnt));
        if (prev == NB - 1) {
            asm volatile("st.relaxed.gpu.u32 [%0], 0;" :: "l"(&g_bar_cnt));
            unsigned d;
            asm volatile("atom.add.release.gpu.u32 %0, [%1], 1;"
                         : "=r"(d) : "l"(&g_bar_gen));
        } else {
            unsigned g;
            do {
                asm volatile("ld.acquire.gpu.u32 %0, [%1];" : "=r"(g) : "l"(&g_bar_gen));
            } while (g == gen);
        }
    }
    __syncthreads();
}

// ---------------- split + A-fragment pack ----------------
__device__ __forceinline__ void split_bf16(float v, __nv_bfloat16& hi, __nv_bfloat16& lo) {
    hi = __float2bfloat16(v);
    lo = __float2bfloat16(v - __bfloat162float(hi));
}
// entry e = (mt*64 + kt)*32 + lane holds 16 bf16: 8 hi then 8 lo
__device__ __forceinline__ void pack_a(__nv_bfloat16* dst, int row, int u,
                                       float vx, float vy)
{
    const int mt = row >> 4, rm = row & 15;
    const int kt = u >> 4,  cm = u & 15;          // u even
    const int lane = (rm & 7) * 4 + ((cm & 7) >> 1);
    const int reg  = (rm >> 3) + ((cm >> 3) & 1) * 2;
    const size_t base = ((size_t)(mt * 64 + kt) * 32 + lane) * 16;
    __nv_bfloat16 hx, lx, hy, ly;
    split_bf16(vx, hx, lx);
    split_bf16(vy, hy, ly);
    __nv_bfloat162 hp; hp.x = hx; hp.y = hy;
    __nv_bfloat162 lp; lp.x = lx; lp.y = ly;
    *(__nv_bfloat162*)&dst[base + reg * 2]     = hp;
    *(__nv_bfloat162*)&dst[base + 8 + reg * 2] = lp;
}

// ---------------- GEMM1 (fp32 SIMT, K=128): h1pk = pack(relu(inputs@We1+be1)) ----
__global__ __launch_bounds__(256, 2)
void sgemm128_pack(const float* __restrict__ A, const float* __restrict__ Bm,
                   const float* __restrict__ bias, int N, int K)
{
    __shared__ float As[8][128];
    __shared__ float Bs[8][128];
    const int tid  = threadIdx.x;
    const int brow = blockIdx.y, bcol = blockIdx.x;
    const int tr = tid >> 4, tc = tid & 15;
    const int aRow = tid >> 1, aCol = (tid & 1) * 4;
    const int bRow = tid >> 5, bCol = (tid & 31) * 4;
    const float* Ap = A + (size_t)(brow * 128) * K;
    const float* Bp = Bm + bcol * 128;

    float acc[8][8];
#pragma unroll
    for (int i = 0; i < 8; i++)
#pragma unroll
        for (int j = 0; j < 8; j++) acc[i][j] = 0.f;

    for (int k0 = 0; k0 < K; k0 += 8) {
        float4 av = *(const float4*)(Ap + (size_t)aRow * K + k0 + aCol);
        As[aCol + 0][aRow] = av.x; As[aCol + 1][aRow] = av.y;
        As[aCol + 2][aRow] = av.z; As[aCol + 3][aRow] = av.w;
        float4 bv = *(const float4*)(Bp + (size_t)(k0 + bRow) * N + bCol);
        *(float4*)&Bs[bRow][bCol] = bv;
        __syncthreads();
#pragma unroll
        for (int kk = 0; kk < 8; kk++) {
            float4 a0 = *(const float4*)&As[kk][tr * 8];
            float4 a1 = *(const float4*)&As[kk][tr * 8 + 4];
            float4 b0 = *(const float4*)&Bs[kk][tc * 8];
            float4 b1 = *(const float4*)&Bs[kk][tc * 8 + 4];
            float ar[8] = {a0.x,a0.y,a0.z,a0.w,a1.x,a1.y,a1.z,a1.w};
            float br[8] = {b0.x,b0.y,b0.z,b0.w,b1.x,b1.y,b1.z,b1.w};
#pragma unroll
            for (int i = 0; i < 8; i++)
#pragma unroll
                for (int j = 0; j < 8; j++)
                    acc[i][j] = fmaf(ar[i], br[j], acc[i][j]);
        }
        __syncthreads();
    }
#pragma unroll
    for (int i = 0; i < 8; i++) {
        int row = brow * 128 + tr * 8 + i;
#pragma unroll
        for (int j = 0; j < 8; j += 2) {
            int col = bcol * 128 + tc * 8 + j;
            float v0 = fmaxf(acc[i][j]     + bias[col],     0.f);
            float v1 = fmaxf(acc[i][j + 1] + bias[col + 1], 0.f);
            pack_a(g_h1pk, row, col, v0, v1);
        }
    }
}

// ---------------- pack weights into split B-fragment layout ----------------
__global__ void pack_weights(const float* __restrict__ W1, const float* __restrict__ Wr,
                             const float* __restrict__ Wk, const float* __restrict__ We2,
                             const float* __restrict__ W2)
{
    const int TOT1 = (N1 / 8) * 64 * 32;   // 1,310,720
    const int TOT2 = (N2 / 8) * 64 * 32;   // 1,048,576
    const int TOT3 = (UU / 8) * 64 * 32;   //   262,144
    int c = blockIdx.x * blockDim.x + threadIdx.x;
    const float* W; int ld; __nv_bfloat16* dst; int cl; int nsub = 0;
    if (c < TOT1) {
        cl = c; dst = g_Wpk1;
        int nt = cl / 2048, l = cl & 31;
        int n = nt * 8 + (l >> 2);
        if (n < 1024) { W = W1; ld = 1024; }
        else          { W = Wr; ld = 4096; nsub = 1024; }
    } else if (c < TOT1 + TOT2) {
        cl = c - TOT1; dst = g_Wpk2; W = Wk; ld = 4096;
    } else if (c < TOT1 + TOT2 + TOT3) {
        cl = c - TOT1 - TOT2; dst = g_We2pk; W = We2; ld = 1024;
    } else if (c < TOT1 + TOT2 + 2 * TOT3) {
        cl = c - TOT1 - TOT2 - TOT3; dst = g_W2pk; W = W2; ld = 1024;
    } else return;

    int nt = cl / 2048, rem = cl % 2048, kt = rem >> 5, l = rem & 31;
    int n  = nt * 8 + (l >> 2) - nsub;
    int k0 = kt * 16 + (l & 3) * 2;
    float w[4];
    w[0] = W[(size_t)(k0    ) * ld + n];
    w[1] = W[(size_t)(k0 + 1) * ld + n];
    w[2] = W[(size_t)(k0 + 8) * ld + n];
    w[3] = W[(size_t)(k0 + 9) * ld + n];
    __nv_bfloat16* o = dst + (size_t)cl * 8;
#pragma unroll
    for (int i = 0; i < 4; i++) split_bf16(w[i], o[i], o[4 + i]);
}

// ---------------- big split-bf16 HMMA: C[16384, N] = Apk @ Wpk ----------------
// one 64x32 tile per block, 8 warps = (mt 0..3, np 0..1)
__global__ __launch_bounds__(256)
void hgemm_big(const __nv_bfloat16* __restrict__ Apk,
               const __nv_bfloat16* __restrict__ Wpk,
               const float* __restrict__ bias, int doRelu, int N,
               __nv_bfloat16* __restrict__ outPk, __half* __restrict__ outH)
{
    const int tiles_n = N / 32;
    const int tm = blockIdx.x / tiles_n, tn = blockIdx.x % tiles_n;
    const int tid = threadIdx.x;
    const int w = tid >> 5, l = tid & 31;
    const int mt = w >> 1, np = w & 1;
    const int mtg = tm * 4 + mt;
    const uint4* a_it  = (const uint4*)Apk + ((size_t)mtg * 2048 + l) * 2;
    const int nt0 = tn * 4 + np * 2;
    const uint4* b0_it = (const uint4*)Wpk + (size_t)nt0 * 2048 + l;
    const uint4* b1_it = b0_it + 2048;

    float d0[4] = {0.f,0.f,0.f,0.f};
    float d1[4] = {0.f,0.f,0.f,0.f};
#pragma unroll 4
    for (int kt = 0; kt < 64; kt++) {
        uint4 aH = a_it[(size_t)kt * 64];
        uint4 aL = a_it[(size_t)kt * 64 + 1];
        uint4 b0 = b0_it[kt * 32];
        uint4 b1 = b1_it[kt * 32];
        uint2 b0H = make_uint2(b0.x, b0.y), b0L = make_uint2(b0.z, b0.w);
        uint2 b1H = make_uint2(b1.x, b1.y), b1L = make_uint2(b1.z, b1.w);
        mma16816(d0, aH, b0H);
        mma16816(d0, aH, b0L);
        mma16816(d0, aL, b0H);
        mma16816(d1, aH, b1H);
        mma16816(d1, aH, b1L);
        mma16816(d1, aL, b1H);
    }
    const int r0 = tm * 64 + mt * 16 + (l >> 2);
    const int c0 = tn * 32 + np * 16 + ((l & 3) << 1);
    float2 bbA = *(const float2*)&bias[c0];
    float2 bbB = *(const float2*)&bias[c0 + 8];
    d0[0] += bbA.x; d0[1] += bbA.y; d0[2] += bbA.x; d0[3] += bbA.y;
    d1[0] += bbB.x; d1[1] += bbB.y; d1[2] += bbB.x; d1[3] += bbB.y;
    if (doRelu) {
#pragma unroll
        for (int i = 0; i < 4; i++) {
            d0[i] = fmaxf(d0[i], 0.f);
            d1[i] = fmaxf(d1[i], 0.f);
        }
    }
    if (outH) {
        *(__half2*)&outH[(size_t)r0 * N + c0]           = __floats2half2_rn(d0[0], d0[1]);
        *(__half2*)&outH[(size_t)(r0 + 8) * N + c0]     = __floats2half2_rn(d0[2], d0[3]);
        *(__half2*)&outH[(size_t)r0 * N + c0 + 8]       = __floats2half2_rn(d1[0], d1[1]);
        *(__half2*)&outH[(size_t)(r0 + 8) * N + c0 + 8] = __floats2half2_rn(d1[2], d1[3]);
    }
    if (outPk) {
        pack_a(outPk, r0,     c0,     d0[0], d0[1]);
        pack_a(outPk, r0 + 8, c0,     d0[2], d0[3]);
        pack_a(outPk, r0,     c0 + 8, d1[0], d1[1]);
        pack_a(outPk, r0 + 8, c0 + 8, d1[2], d1[3]);
    }
}

// ---------------- init ----------------
__global__ void init_state(float* __restrict__ out)
{
    int idx = blockIdx.x * blockDim.x + threadIdx.x;
    if (idx < BB * UU) {
        g_c[idx] = 0.f;
        g_hpk[idx] = __float2bfloat16(0.f);
        g_hpk[BB * UU + idx] = __float2bfloat16(0.f);
    }
    if (idx < SEQ * BB) out[idx] = 0.f;
}

// ---------------- decode step GEMM (split-bf16 HMMA, persistent) ----------------
__device__ __forceinline__ void hgemm_phase(const __nv_bfloat16* __restrict__ Apk,
                                            const __nv_bfloat16* __restrict__ Wpk,
                                            const float* __restrict__ bias,
                                            float* __restrict__ C,
                                            int ntiles, int ldc)
{
    const int tid = threadIdx.x;
    const int w = tid >> 5, l = tid & 31;
    const int mt = w >> 1, np = w & 1;
    const uint4* ap = (const uint4*)Apk;
    const uint4* bp = (const uint4*)Wpk;

    for (int bt = blockIdx.x; bt < ntiles; bt += NB) {
        const int n0  = bt * 32;
        const int nt0 = (n0 >> 3) + np * 2;
        float d0[4] = {0.f,0.f,0.f,0.f};
        float d1[4] = {0.f,0.f,0.f,0.f};
        const uint4* a_it  = ap + ((size_t)mt * 2048 + l) * 2;
        const uint4* b0_it = bp + (size_t)nt0 * 2048 + l;
        const uint4* b1_it = b0_it + 2048;
#pragma unroll 4
        for (int kt = 0; kt < 64; kt++) {
            uint4 aH = a_it[kt * 64];
            uint4 aL = a_it[kt * 64 + 1];
            uint4 b0 = b0_it[kt * 32];
            uint4 b1 = b1_it[kt * 32];
            uint2 b0H = make_uint2(b0.x, b0.y), b0L = make_uint2(b0.z, b0.w);
            uint2 b1H = make_uint2(b1.x, b1.y), b1L = make_uint2(b1.z, b1.w);
            mma16816(d0, aH, b0H);
            mma16816(d0, aH, b0L);
            mma16816(d0, aL, b0H);
            mma16816(d1, aH, b1H);
            mma16816(d1, aH, b1L);
            mma16816(d1, aL, b1H);
        }
        const int r0 = mt * 16 + (l >> 2);
        const int c0 = n0 + np * 16 + ((l & 3) << 1);
        if (bias && n0 < 1024) {
            float2 bbA = *(const float2*)&bias[c0];
            float2 bbB = *(const float2*)&bias[c0 + 8];
            d0[0] += bbA.x; d0[1] += bbA.y; d0[2] += bbA.x; d0[3] += bbA.y;
            d1[0] += bbB.x; d1[1] += bbB.y; d1[2] += bbB.x; d1[3] += bbB.y;
        }
        *(float2*)&C[(size_t)r0 * ldc + c0]           = make_float2(d0[0], d0[1]);
        *(float2*)&C[(size_t)(r0 + 8) * ldc + c0]     = make_float2(d0[2], d0[3]);
        *(float2*)&C[(size_t)r0 * ldc + c0 + 8]       = make_float2(d1[0], d1[1]);
        *(float2*)&C[(size_t)(r0 + 8) * ldc + c0 + 8] = make_float2(d1[2], d1[3]);
    }
}

// ---------------- persistent decode ----------------
__global__ __launch_bounds__(256, 1)
void decode_persistent(const float* __restrict__ b1, const float* __restrict__ V,
                       const float* __restrict__ bl, const float* __restrict__ Wo,
                       const float* __restrict__ bo, float* __restrict__ out)
{
    __shared__ float sm[256];
    __shared__ float red[8];
    const int tid  = threadIdx.x;
    const int bid  = blockIdx.x;
    const int warp = tid >> 5, lane = tid & 31;
    const int b2   = bid >> 1;
    const int half = bid & 1;

    // V slice in registers: vr[it*8+j] = V[it*256 + lane*8 + j]
    float vr[32];
#pragma unroll
    for (int it = 0; it < 4; it++) {
        float4 a = *(const float4*)&V[it * 256 + lane * 8];
        float4 b = *(const float4*)&V[it * 256 + lane * 8 + 4];
        vr[it*8+0]=a.x; vr[it*8+1]=a.y; vr[it*8+2]=a.z; vr[it*8+3]=a.w;
        vr[it*8+4]=b.x; vr[it*8+5]=b.y; vr[it*8+6]=b.z; vr[it*8+7]=b.w;
    }

    for (int s = 0; s < SEQ; s++) {
        // ---- phase 1: g_q = h @ [W1|Wr] (+b1 on cols<1024) ----
        hgemm_phase(g_hpk, g_Wpk1, b1, g_q, N1 / 32, N1);
        grid_bar();

        // ---- phase 2: attention scores (fp16 keys) ----
        {
            float qr[32];
#pragma unroll
            for (int it = 0; it < 4; it++) {
                float4 a = *(const float4*)&g_q[b2 * N1 + it * 256 + lane * 8];
                float4 b = *(const float4*)&g_q[b2 * N1 + it * 256 + lane * 8 + 4];
                qr[it*8+0]=a.x; qr[it*8+1]=a.y; qr[it*8+2]=a.z; qr[it*8+3]=a.w;
                qr[it*8+4]=b.x; qr[it*8+5]=b.y; qr[it*8+6]=b.z; qr[it*8+7]=b.w;
            }
            for (int t = warp; t < 128; t += 8) {
                const int tt = half * 128 + t;
                const uint4* kp = (const uint4*)(g_keh + ((size_t)(b2 * 256 + tt)) * 1024);
                float s0 = 0.f;
#pragma unroll
                for (int it = 0; it < 4; it++) {
                    uint4 kv = kp[it * 32 + lane];
                    float2 f0 = __half22float2(*(__half2*)&kv.x);
                    float2 f1 = __half22float2(*(__half2*)&kv.y);
                    float2 f2 = __half22float2(*(__half2*)&kv.z);
                    float2 f3 = __half22float2(*(__half2*)&kv.w);
                    s0 += vr[it*8+0] * tanh_hw(qr[it*8+0] + f0.x);
                    s0 += vr[it*8+1] * tanh_hw(qr[it*8+1] + f0.y);
                    s0 += vr[it*8+2] * tanh_hw(qr[it*8+2] + f1.x);
                    s0 += vr[it*8+3] * tanh_hw(qr[it*8+3] + f1.y);
                    s0 += vr[it*8+4] * tanh_hw(qr[it*8+4] + f2.x);
                    s0 += vr[it*8+5] * tanh_hw(qr[it*8+5] + f2.y);
                    s0 += vr[it*8+6] * tanh_hw(qr[it*8+6] + f3.x);
                    s0 += vr[it*8+7] * tanh_hw(qr[it*8+7] + f3.y);
                }
#pragma unroll
                for (int o = 16; o; o >>= 1) s0 += __shfl_xor_sync(0xffffffffu, s0, o);
                if (!lane) g_sc[b2 * 256 + tt] = s0;
            }
        }
        grid_bar();

        // ---- phase 3: softmax + ctx (fp16 x), pack ctx split A-frags ----
        {
            float v = g_sc[b2 * 256 + tid];
            float m = v;
#pragma unroll
            for (int o = 16; o; o >>= 1) m = fmaxf(m, __shfl_xor_sync(0xffffffffu, m, o));
            if (!lane) red[warp] = m;
            __syncthreads();
            float bm = red[0];
#pragma unroll
            for (int w = 1; w < 8; w++) bm = fmaxf(bm, red[w]);
            __syncthreads();
            float e = __expf(v - bm);
            float ss = e;
#pragma unroll
            for (int o = 16; o; o >>= 1) ss += __shfl_xor_sync(0xffffffffu, ss, o);
            if (!lane) red[warp] = ss;
            __syncthreads();
            float bs = 0.f;
#pragma unroll
            for (int w = 0; w < 8; w++) bs += red[w];
            sm[tid] = __fdividef(e, bs);
            __syncthreads();

            const int u2 = half * 512 + tid * 2;
            const __half2* xb = (const __half2*)(g_xh + (size_t)b2 * 256 * 1024 + u2);
            float ax = 0.f, ay = 0.f;
#pragma unroll 4
            for (int t = 0; t < 256; t++) {
                float2 xv = __half22float2(xb[(size_t)t * 512]);
                float wt = sm[t];
                ax = fmaf(wt, xv.x, ax);
                ay = fmaf(wt, xv.y, ay);
            }
            pack_a(g_cpk, b2, u2, ax, ay);
            __syncthreads();
        }
        grid_bar();

        // ---- phase 4: g_z = ctx @ Wk ----
        hgemm_phase(g_cpk, g_Wpk2, (const float*)0, g_z, N2 / 32, N2);
        grid_bar();

        // ---- phase 5: LSTM gates + state + projection; pack new h ----
        {
            const int j0 = half * 512 + tid * 2;
            const float* zb = g_z + (size_t)b2 * N2;
            const float* hb = g_q + (size_t)b2 * N1 + 1024;
            float2 a, b;
            a = *(const float2*)&zb[j0];        b = *(const float2*)&hb[j0];
            float2 zi = { bl[j0]   + a.x + b.x, bl[j0+1]   + a.y + b.y };
            a = *(const float2*)&zb[1024+j0];   b = *(const float2*)&hb[1024+j0];
            float2 zf = { bl[1024+j0] + a.x + b.x, bl[1024+j0+1] + a.y + b.y };
            a = *(const float2*)&zb[2048+j0];   b = *(const float2*)&hb[2048+j0];
            float2 zg = { bl[2048+j0] + a.x + b.x, bl[2048+j0+1] + a.y + b.y };
            a = *(const float2*)&zb[3072+j0];   b = *(const float2*)&hb[3072+j0];
            float2 zo = { bl[3072+j0] + a.x + b.x, bl[3072+j0+1] + a.y + b.y };

            float2 cold = *(const float2*)&g_c[b2 * 1024 + j0];
            float cx = sigf(zf.x) * cold.x + sigf(zi.x) * fast_tanh(zg.x);
            float cy = sigf(zf.y) * cold.y + sigf(zi.y) * fast_tanh(zg.y);
            float hx = sigf(zo.x) * fast_tanh(cx);
            float hy = sigf(zo.y) * fast_tanh(cy);
            *(float2*)&g_c[b2 * 1024 + j0] = make_float2(cx, cy);
            pack_a(g_hpk, b2, j0, hx, hy);

            float p = hx * Wo[j0] + hy * Wo[j0 + 1];
            if (tid == 0 && half == 0) p += bo[0];
#pragma unroll
            for (int o = 16; o; o >>= 1) p += __shfl_xor_sync(0xffffffffu, p, o);
            if (!lane) red[warp] = p;
            __syncthreads();
            if (tid == 0) {
                float acc = 0.f;
#pragma unroll
                for (int w = 0; w < 8; w++) acc += red[w];
                atomicAdd(&out[s * 64 + b2], acc);
            }
            __syncthreads();
        }
        grid_bar();
    }
}

// ---------------- host launcher ----------------
extern "C" void kernel_launch(void* const* d_in, const int* in_sizes, int n_in,
                              void* d_out, int out_size)
{
    const float* inputs = (const float*)d_in[0];
    const float* We1 = (const float*)d_in[1];  const float* be1 = (const float*)d_in[2];
    const float* We2 = (const float*)d_in[3];  const float* be2 = (const float*)d_in[4];
    const float* W1  = (const float*)d_in[5];  const float* b1  = (const float*)d_in[6];
    const float* W2  = (const float*)d_in[7];  const float* b2k = (const float*)d_in[8];
    const float* V   = (const float*)d_in[9];  /* bV shift-invariant in softmax */
    const float* Wk  = (const float*)d_in[11]; const float* Wr  = (const float*)d_in[12];
    const float* bl  = (const float*)d_in[13]; const float* Wo  = (const float*)d_in[14];
    const float* bo  = (const float*)d_in[15];
    float* out = (float*)d_out;

    void *p_h1pk, *p_xpk, *p_xh, *p_keh, *p_We2pk, *p_W2pk;
    cudaGetSymbolAddress(&p_h1pk,  g_h1pk);
    cudaGetSymbolAddress(&p_xpk,   g_xpk);
    cudaGetSymbolAddress(&p_xh,    g_xh);
    cudaGetSymbolAddress(&p_keh,   g_keh);
    cudaGetSymbolAddress(&p_We2pk, g_We2pk);
    cudaGetSymbolAddress(&p_W2pk,  g_W2pk);

    // weights -> split fragments (all 5 step/precompute matrices)
    pack_weights<<<5632, 512>>>(W1, Wr, Wk, We2, W2);
    // GEMM1 (fp32 SIMT): h1pk = pack(relu(inputs@We1+be1))
    sgemm128_pack<<<dim3(UU / 128, NROW / 128), 256>>>(inputs, We1, be1, UU, DINN);
    // GEMM2 (HMMA): x = relu(h1@We2+be2) -> xpk + xh(fp16)
    hgemm_big<<<(NROW / 64) * (UU / 32), 256>>>(
        (const __nv_bfloat16*)p_h1pk, (const __nv_bfloat16*)p_We2pk, be2, 1, UU,
        (__nv_bfloat16*)p_xpk, (__half*)p_xh);
    // GEMM3 (HMMA): keys = x@W2+b2 -> keh(fp16)
    hgemm_big<<<(NROW / 64) * (UU / 32), 256>>>(
        (const __nv_bfloat16*)p_xpk, (const __nv_bfloat16*)p_W2pk, b2k, 0, UU,
        (__nv_bfloat16*)0, (__half*)p_keh);
    init_state<<<64, 1024>>>(out);
    decode_persistent<<<NB, 256>>>(b1, V, bl, Wo, bo, out);
}

// round 8
// speedup vs baseline: 1.7169x; 1.0568x over previous
#include <cuda_runtime.h>
#include <cuda_bf16.h>
#include <cuda_fp16.h>
#include <math.h>

#define BB   64
#define TT   256
#define DINN 128
#define UU   1024
#define SEQ  256
#define NROW (BB*TT)
#define NB   128
#define N1   5120       // [W1 | Wr]
#define N2   4096       // Wk

// ---------------- device scratch ----------------
__device__ __nv_bfloat16 g_h1pk[(size_t)NROW * UU * 2];   // h1 A-frags
__device__ __nv_bfloat16 g_xpk [(size_t)NROW * UU * 2];   // x  A-frags
__device__ __half g_xh [(size_t)NROW * UU];               // x  fp16 linear
__device__ __half g_keh[(size_t)NROW * UU];               // keys fp16 linear
__device__ __nv_bfloat16 g_Wpk1 [(size_t)UU * N1 * 2];    // B-frags [W1|Wr]
__device__ __nv_bfloat16 g_Wpk2 [(size_t)UU * N2 * 2];    // B-frags Wk
__device__ __nv_bfloat16 g_We2pk[(size_t)UU * UU * 2];    // B-frags We2
__device__ __nv_bfloat16 g_W2pk [(size_t)UU * UU * 2];    // B-frags W2
__device__ __nv_bfloat16 g_hpk[BB * UU * 2];              // A-frags h
__device__ __nv_bfloat16 g_cpk[BB * UU * 2];              // A-frags ctx
__device__ float g_q [BB * N1];
__device__ float g_z [BB * N2];
__device__ float g_c [BB * UU];
__device__ unsigned g_bar_cnt = 0;
__device__ unsigned g_bar_gen = 0;
__device__ unsigned g_qcnt   = 0;

// ---------------- helpers ----------------
__device__ __forceinline__ float tanh_hw(float x) {
    float y; asm("tanh.approx.f32 %0, %1;" : "=f"(y) : "f"(x)); return y;
}
__device__ __forceinline__ float fast_tanh(float x) {
    float e = __expf(2.0f * x);
    return 1.0f - __fdividef(2.0f, e + 1.0f);
}
__device__ __forceinline__ float sigf(float x) {
    return __fdividef(1.0f, 1.0f + __expf(-x));
}

__device__ __forceinline__ void mma16816(float d[4], const uint4& a, const uint2& b) {
    asm("mma.sync.aligned.m16n8k16.row.col.f32.bf16.bf16.f32 "
        "{%0,%1,%2,%3},{%4,%5,%6,%7},{%8,%9},{%0,%1,%2,%3};"
        : "+f"(d[0]), "+f"(d[1]), "+f"(d[2]), "+f"(d[3])
        : "r"(a.x), "r"(a.y), "r"(a.z), "r"(a.w), "r"(b.x), "r"(b.y));
}

// grid barrier: bar.sync (block fence) + thread0 release-arrive / acquire-spin
__device__ __forceinline__ void grid_bar() {
    __syncthreads();
    if (threadIdx.x == 0) {
        unsigned gen;
        asm volatile("ld.acquire.gpu.u32 %0, [%1];" : "=r"(gen) : "l"(&g_bar_gen));
        unsigned prev;
        asm volatile("atom.add.release.gpu.u32 %0, [%1], 1;"
                     : "=r"(prev) : "l"(&g_bar_cnt));
        if (prev == NB - 1) {
            asm volatile("st.relaxed.gpu.u32 [%0], 0;" :: "l"(&g_bar_cnt));
            unsigned d;
            asm volatile("atom.add.release.gpu.u32 %0, [%1], 1;"
                         : "=r"(d) : "l"(&g_bar_gen));
        } else {
            unsigned g;
            do {
                asm volatile("ld.acquire.gpu.u32 %0, [%1];" : "=r"(g) : "l"(&g_bar_gen));
            } while (g == gen);
        }
    }
    __syncthreads();
}

// ---------------- split + A-fragment pack ----------------
__device__ __forceinline__ void split_bf16(float v, __nv_bfloat16& hi, __nv_bfloat16& lo) {
    hi = __float2bfloat16(v);
    lo = __float2bfloat16(v - __bfloat162float(hi));
}
__device__ __forceinline__ void pack_a(__nv_bfloat16* dst, int row, int u,
                                       float vx, float vy)
{
    const int mt = row >> 4, rm = row & 15;
    const int kt = u >> 4,  cm = u & 15;          // u even
    const int lane = (rm & 7) * 4 + ((cm & 7) >> 1);
    const int reg  = (rm >> 3) + ((cm >> 3) & 1) * 2;
    const size_t base = ((size_t)(mt * 64 + kt) * 32 + lane) * 16;
    __nv_bfloat16 hx, lx, hy, ly;
    split_bf16(vx, hx, lx);
    split_bf16(vy, hy, ly);
    __nv_bfloat162 hp; hp.x = hx; hp.y = hy;
    __nv_bfloat162 lp; lp.x = lx; lp.y = ly;
    *(__nv_bfloat162*)&dst[base + reg * 2]     = hp;
    *(__nv_bfloat162*)&dst[base + 8 + reg * 2] = lp;
}

// ---------------- GEMM1 (fp32 SIMT, K=128): h1pk = pack(relu(inputs@We1+be1)) ----
__global__ __launch_bounds__(256, 2)
void sgemm128_pack(const float* __restrict__ A, const float* __restrict__ Bm,
                   const float* __restrict__ bias, int N, int K)
{
    __shared__ float As[8][128];
    __shared__ float Bs[8][128];
    const int tid  = threadIdx.x;
    const int brow = blockIdx.y, bcol = blockIdx.x;
    const int tr = tid >> 4, tc = tid & 15;
    const int aRow = tid >> 1, aCol = (tid & 1) * 4;
    const int bRow = tid >> 5, bCol = (tid & 31) * 4;
    const float* Ap = A + (size_t)(brow * 128) * K;
    const float* Bp = Bm + bcol * 128;

    float acc[8][8];
#pragma unroll
    for (int i = 0; i < 8; i++)
#pragma unroll
        for (int j = 0; j < 8; j++) acc[i][j] = 0.f;

    for (int k0 = 0; k0 < K; k0 += 8) {
        float4 av = *(const float4*)(Ap + (size_t)aRow * K + k0 + aCol);
        As[aCol + 0][aRow] = av.x; As[aCol + 1][aRow] = av.y;
        As[aCol + 2][aRow] = av.z; As[aCol + 3][aRow] = av.w;
        float4 bv = *(const float4*)(Bp + (size_t)(k0 + bRow) * N + bCol);
        *(float4*)&Bs[bRow][bCol] = bv;
        __syncthreads();
#pragma unroll
        for (int kk = 0; kk < 8; kk++) {
            float4 a0 = *(const float4*)&As[kk][tr * 8];
            float4 a1 = *(const float4*)&As[kk][tr * 8 + 4];
            float4 b0 = *(const float4*)&Bs[kk][tc * 8];
            float4 b1 = *(const float4*)&Bs[kk][tc * 8 + 4];
            float ar[8] = {a0.x,a0.y,a0.z,a0.w,a1.x,a1.y,a1.z,a1.w};
            float br[8] = {b0.x,b0.y,b0.z,b0.w,b1.x,b1.y,b1.z,b1.w};
#pragma unroll
            for (int i = 0; i < 8; i++)
#pragma unroll
                for (int j = 0; j < 8; j++)
                    acc[i][j] = fmaf(ar[i], br[j], acc[i][j]);
        }
        __syncthreads();
    }
#pragma unroll
    for (int i = 0; i < 8; i++) {
        int row = brow * 128 + tr * 8 + i;
#pragma unroll
        for (int j = 0; j < 8; j += 2) {
            int col = bcol * 128 + tc * 8 + j;
            float v0 = fmaxf(acc[i][j]     + bias[col],     0.f);
            float v1 = fmaxf(acc[i][j + 1] + bias[col + 1], 0.f);
            pack_a(g_h1pk, row, col, v0, v1);
        }
    }
}

// ---------------- pack weights into split B-fragment layout ----------------
__global__ void pack_weights(const float* __restrict__ W1, const float* __restrict__ Wr,
                             const float* __restrict__ Wk, const float* __restrict__ We2,
                             const float* __restrict__ W2)
{
    const int TOT1 = (N1 / 8) * 64 * 32;
    const int TOT2 = (N2 / 8) * 64 * 32;
    const int TOT3 = (UU / 8) * 64 * 32;
    int c = blockIdx.x * blockDim.x + threadIdx.x;
    const float* W; int ld; __nv_bfloat16* dst; int cl; int nsub = 0;
    if (c < TOT1) {
        cl = c; dst = g_Wpk1;
        int nt = cl / 2048, l = cl & 31;
        int n = nt * 8 + (l >> 2);
        if (n < 1024) { W = W1; ld = 1024; }
        else          { W = Wr; ld = 4096; nsub = 1024; }
    } else if (c < TOT1 + TOT2) {
        cl = c - TOT1; dst = g_Wpk2; W = Wk; ld = 4096;
    } else if (c < TOT1 + TOT2 + TOT3) {
        cl = c - TOT1 - TOT2; dst = g_We2pk; W = We2; ld = 1024;
    } else if (c < TOT1 + TOT2 + 2 * TOT3) {
        cl = c - TOT1 - TOT2 - TOT3; dst = g_W2pk; W = W2; ld = 1024;
    } else return;

    int nt = cl / 2048, rem = cl % 2048, kt = rem >> 5, l = rem & 31;
    int n  = nt * 8 + (l >> 2) - nsub;
    int k0 = kt * 16 + (l & 3) * 2;
    float w[4];
    w[0] = W[(size_t)(k0    ) * ld + n];
    w[1] = W[(size_t)(k0 + 1) * ld + n];
    w[2] = W[(size_t)(k0 + 8) * ld + n];
    w[3] = W[(size_t)(k0 + 9) * ld + n];
    __nv_bfloat16* o = dst + (size_t)cl * 8;
#pragma unroll
    for (int i = 0; i < 4; i++) split_bf16(w[i], o[i], o[4 + i]);
}

// ---------------- big split-bf16 HMMA: C[16384, N] = Apk @ Wpk ----------------
__global__ __launch_bounds__(256)
void hgemm_big(const __nv_bfloat16* __restrict__ Apk,
               const __nv_bfloat16* __restrict__ Wpk,
               const float* __restrict__ bias, int doRelu, int N,
               __nv_bfloat16* __restrict__ outPk, __half* __restrict__ outH)
{
    const int tiles_n = N / 32;
    const int tm = blockIdx.x / tiles_n, tn = blockIdx.x % tiles_n;
    const int tid = threadIdx.x;
    const int w = tid >> 5, l = tid & 31;
    const int mt = w >> 1, np = w & 1;
    const int mtg = tm * 4 + mt;
    const uint4* a_it  = (const uint4*)Apk + ((size_t)mtg * 2048 + l) * 2;
    const int nt0 = tn * 4 + np * 2;
    const uint4* b0_it = (const uint4*)Wpk + (size_t)nt0 * 2048 + l;
    const uint4* b1_it = b0_it + 2048;

    float d0[4] = {0.f,0.f,0.f,0.f};
    float d1[4] = {0.f,0.f,0.f,0.f};
#pragma unroll 4
    for (int kt = 0; kt < 64; kt++) {
        uint4 aH = a_it[(size_t)kt * 64];
        uint4 aL = a_it[(size_t)kt * 64 + 1];
        uint4 b0 = b0_it[kt * 32];
        uint4 b1 = b1_it[kt * 32];
        uint2 b0H = make_uint2(b0.x, b0.y), b0L = make_uint2(b0.z, b0.w);
        uint2 b1H = make_uint2(b1.x, b1.y), b1L = make_uint2(b1.z, b1.w);
        mma16816(d0, aH, b0H);
        mma16816(d0, aH, b0L);
        mma16816(d0, aL, b0H);
        mma16816(d1, aH, b1H);
        mma16816(d1, aH, b1L);
        mma16816(d1, aL, b1H);
    }
    const int r0 = tm * 64 + mt * 16 + (l >> 2);
    const int c0 = tn * 32 + np * 16 + ((l & 3) << 1);
    float2 bbA = *(const float2*)&bias[c0];
    float2 bbB = *(const float2*)&bias[c0 + 8];
    d0[0] += bbA.x; d0[1] += bbA.y; d0[2] += bbA.x; d0[3] += bbA.y;
    d1[0] += bbB.x; d1[1] += bbB.y; d1[2] += bbB.x; d1[3] += bbB.y;
    if (doRelu) {
#pragma unroll
        for (int i = 0; i < 4; i++) {
            d0[i] = fmaxf(d0[i], 0.f);
            d1[i] = fmaxf(d1[i], 0.f);
        }
    }
    if (outH) {
        *(__half2*)&outH[(size_t)r0 * N + c0]           = __floats2half2_rn(d0[0], d0[1]);
        *(__half2*)&outH[(size_t)(r0 + 8) * N + c0]     = __floats2half2_rn(d0[2], d0[3]);
        *(__half2*)&outH[(size_t)r0 * N + c0 + 8]       = __floats2half2_rn(d1[0], d1[1]);
        *(__half2*)&outH[(size_t)(r0 + 8) * N + c0 + 8] = __floats2half2_rn(d1[2], d1[3]);
    }
    if (outPk) {
        pack_a(outPk, r0,     c0,     d0[0], d0[1]);
        pack_a(outPk, r0 + 8, c0,     d0[2], d0[3]);
        pack_a(outPk, r0,     c0 + 8, d1[0], d1[1]);
        pack_a(outPk, r0 + 8, c0 + 8, d1[2], d1[3]);
    }
}

// ---------------- init ----------------
__global__ void init_state(float* __restrict__ out)
{
    int idx = blockIdx.x * blockDim.x + threadIdx.x;
    if (idx < BB * UU) {
        g_c[idx] = 0.f;
        g_hpk[idx] = __float2bfloat16(0.f);
        g_hpk[BB * UU + idx] = __float2bfloat16(0.f);
    }
    if (idx < SEQ * BB) out[idx] = 0.f;
    if (idx == 0) { g_qcnt = 0; g_bar_cnt = 0; }
}

// ---------------- one 64x32 step-GEMM tile, dual accumulator chains ----------
__device__ __forceinline__ void hgemm_tile(const __nv_bfloat16* __restrict__ Apk,
                                           const __nv_bfloat16* __restrict__ Wpk,
                                           const float* __restrict__ bias,
                                           float* __restrict__ C, int ldc, int bt)
{
    const int tid = threadIdx.x;
    const int w = tid >> 5, l = tid & 31;
    const int mt = w >> 1, np = w & 1;
    const uint4* ap = (const uint4*)Apk + ((size_t)mt * 2048 + l) * 2;
    const int n0  = bt * 32;
    const int nt0 = (n0 >> 3) + np * 2;
    const uint4* b0p = (const uint4*)Wpk + (size_t)nt0 * 2048 + l;
    const uint4* b1p = b0p + 2048;

    float d0a[4] = {0.f,0.f,0.f,0.f}, d0b[4] = {0.f,0.f,0.f,0.f};
    float d1a[4] = {0.f,0.f,0.f,0.f}, d1b[4] = {0.f,0.f,0.f,0.f};
#pragma unroll 2
    for (int kt = 0; kt < 64; kt += 2) {
        uint4 aH0 = ap[kt * 64],        aL0 = ap[kt * 64 + 1];
        uint4 aH1 = ap[(kt + 1) * 64],  aL1 = ap[(kt + 1) * 64 + 1];
        uint4 b00 = b0p[kt * 32],       b10 = b1p[kt * 32];
        uint4 b01 = b0p[(kt + 1) * 32], b11 = b1p[(kt + 1) * 32];
        uint2 b00H = make_uint2(b00.x, b00.y), b00L = make_uint2(b00.z, b00.w);
        uint2 b10H = make_uint2(b10.x, b10.y), b10L = make_uint2(b10.z, b10.w);
        uint2 b01H = make_uint2(b01.x, b01.y), b01L = make_uint2(b01.z, b01.w);
        uint2 b11H = make_uint2(b11.x, b11.y), b11L = make_uint2(b11.z, b11.w);
        mma16816(d0a, aH0, b00H);
        mma16816(d0b, aH1, b01H);
        mma16816(d1a, aH0, b10H);
        mma16816(d1b, aH1, b11H);
        mma16816(d0a, aH0, b00L);
        mma16816(d0b, aH1, b01L);
        mma16816(d1a, aH0, b10L);
        mma16816(d1b, aH1, b11L);
        mma16816(d0a, aL0, b00H);
        mma16816(d0b, aL1, b01H);
        mma16816(d1a, aL0, b10H);
        mma16816(d1b, aL1, b11H);
    }
    float d0[4], d1[4];
#pragma unroll
    for (int i = 0; i < 4; i++) { d0[i] = d0a[i] + d0b[i]; d1[i] = d1a[i] + d1b[i]; }

    const int r0 = mt * 16 + (l >> 2);
    const int c0 = n0 + np * 16 + ((l & 3) << 1);
    if (bias && n0 < 1024) {
        float2 bbA = *(const float2*)&bias[c0];
        float2 bbB = *(const float2*)&bias[c0 + 8];
        d0[0] += bbA.x; d0[1] += bbA.y; d0[2] += bbA.x; d0[3] += bbA.y;
        d1[0] += bbB.x; d1[1] += bbB.y; d1[2] += bbB.x; d1[3] += bbB.y;
    }
    *(float2*)&C[(size_t)r0 * ldc + c0]           = make_float2(d0[0], d0[1]);
    *(float2*)&C[(size_t)(r0 + 8) * ldc + c0]     = make_float2(d0[2], d0[3]);
    *(float2*)&C[(size_t)r0 * ldc + c0 + 8]       = make_float2(d1[0], d1[1]);
    *(float2*)&C[(size_t)(r0 + 8) * ldc + c0 + 8] = make_float2(d1[2], d1[3]);
}

// ---------------- persistent decode ----------------
// Blocks 0..63   = A-blocks: fused attention (scores+softmax+ctx) for batch=bid.
// Blocks 64..127 = G-blocks: q tiles (0..31) then hr tiles (32..159), overlapped
//                  with the A-blocks' attention via the g_qcnt flag.
__global__ __launch_bounds__(256, 1)
void decode_persistent(const float* __restrict__ b1, const float* __restrict__ V,
                       const float* __restrict__ bl, const float* __restrict__ Wo,
                       const float* __restrict__ bo, float* __restrict__ out)
{
    __shared__ float sc[256];
    __shared__ float red[8];
    const int tid  = threadIdx.x;
    const int bid  = blockIdx.x;
    const int warp = tid >> 5, lane = tid & 31;
    const bool isA = bid < 64;
    const int gb   = bid - 64;

    // V slice in registers (A-blocks use it every step)
    float vr[32];
#pragma unroll
    for (int it = 0; it < 4; it++) {
        float4 a = *(const float4*)&V[it * 256 + lane * 8];
        float4 b = *(const float4*)&V[it * 256 + lane * 8 + 4];
        vr[it*8+0]=a.x; vr[it*8+1]=a.y; vr[it*8+2]=a.z; vr[it*8+3]=a.w;
        vr[it*8+4]=b.x; vr[it*8+5]=b.y; vr[it*8+6]=b.z; vr[it*8+7]=b.w;
    }

    for (int s = 0; s < SEQ; s++) {
        if (!isA) {
            // ---- G-blocks: q tiles first (signal), then hr tiles ----
            if (gb < 32) {
                hgemm_tile(g_hpk, g_Wpk1, b1, g_q, N1, gb);       // q tile
                __syncthreads();
                if (tid == 0) {
                    unsigned d;
                    asm volatile("atom.add.release.gpu.u32 %0, [%1], 1;"
                                 : "=r"(d) : "l"(&g_qcnt));
                }
                hgemm_tile(g_hpk, g_Wpk1, (const float*)0, g_q, N1, 32 + gb);
            } else {
                const int t0 = 64 + (gb - 32) * 3;
                hgemm_tile(g_hpk, g_Wpk1, (const float*)0, g_q, N1, t0);
                hgemm_tile(g_hpk, g_Wpk1, (const float*)0, g_q, N1, t0 + 1);
                hgemm_tile(g_hpk, g_Wpk1, (const float*)0, g_q, N1, t0 + 2);
            }
        } else {
            // ---- A-blocks: wait for q, then fused attention for batch=bid ----
            const int b = bid;
            if (tid == 0) {
                const unsigned target = 32u * (unsigned)(s + 1);
                unsigned g;
                do {
                    asm volatile("ld.acquire.gpu.u32 %0, [%1];" : "=r"(g) : "l"(&g_qcnt));
                } while (g < target);
            }
            __syncthreads();

            // q slice into registers
            float qr[32];
#pragma unroll
            for (int it = 0; it < 4; it++) {
                float4 a = *(const float4*)&g_q[b * N1 + it * 256 + lane * 8];
                float4 bq = *(const float4*)&g_q[b * N1 + it * 256 + lane * 8 + 4];
                qr[it*8+0]=a.x;  qr[it*8+1]=a.y;  qr[it*8+2]=a.z;  qr[it*8+3]=a.w;
                qr[it*8+4]=bq.x; qr[it*8+5]=bq.y; qr[it*8+6]=bq.z; qr[it*8+7]=bq.w;
            }
            // scores: 256 t over 8 warps
            for (int t = warp; t < 256; t += 8) {
                const uint4* kp = (const uint4*)(g_keh + ((size_t)(b * 256 + t)) * 1024);
                float s0 = 0.f;
#pragma unroll
                for (int it = 0; it < 4; it++) {
                    uint4 kv = kp[it * 32 + lane];
                    float2 f0 = __half22float2(*(__half2*)&kv.x);
                    float2 f1 = __half22float2(*(__half2*)&kv.y);
                    float2 f2 = __half22float2(*(__half2*)&kv.z);
                    float2 f3 = __half22float2(*(__half2*)&kv.w);
                    s0 += vr[it*8+0] * tanh_hw(qr[it*8+0] + f0.x);
                    s0 += vr[it*8+1] * tanh_hw(qr[it*8+1] + f0.y);
                    s0 += vr[it*8+2] * tanh_hw(qr[it*8+2] + f1.x);
                    s0 += vr[it*8+3] * tanh_hw(qr[it*8+3] + f1.y);
                    s0 += vr[it*8+4] * tanh_hw(qr[it*8+4] + f2.x);
                    s0 += vr[it*8+5] * tanh_hw(qr[it*8+5] + f2.y);
                    s0 += vr[it*8+6] * tanh_hw(qr[it*8+6] + f3.x);
                    s0 += vr[it*8+7] * tanh_hw(qr[it*8+7] + f3.y);
                }
#pragma unroll
                for (int o = 16; o; o >>= 1) s0 += __shfl_xor_sync(0xffffffffu, s0, o);
                if (!lane) sc[t] = s0;
            }
            __syncthreads();

            // softmax over 256 (in smem)
            {
                float v = sc[tid];
                float m = v;
#pragma unroll
                for (int o = 16; o; o >>= 1) m = fmaxf(m, __shfl_xor_sync(0xffffffffu, m, o));
                if (!lane) red[warp] = m;
                __syncthreads();
                float bm = red[0];
#pragma unroll
                for (int w2 = 1; w2 < 8; w2++) bm = fmaxf(bm, red[w2]);
                __syncthreads();
                float e = __expf(v - bm);
                float ss = e;
#pragma unroll
                for (int o = 16; o; o >>= 1) ss += __shfl_xor_sync(0xffffffffu, ss, o);
                if (!lane) red[warp] = ss;
                __syncthreads();
                float bs = 0.f;
#pragma unroll
                for (int w2 = 0; w2 < 8; w2++) bs += red[w2];
                sc[tid] = __fdividef(e, bs);
            }
            __syncthreads();

            // ctx: thread handles u0..u0+3
            {
                const int u0 = tid * 4;
                const uint2* xb = (const uint2*)(g_xh + (size_t)b * 256 * 1024 + u0);
                float a0 = 0.f, a1 = 0.f, a2 = 0.f, a3 = 0.f;
#pragma unroll 4
                for (int t = 0; t < 256; t++) {
                    uint2 xv = xb[(size_t)t * 256];
                    float2 x0 = __half22float2(*(__half2*)&xv.x);
                    float2 x1 = __half22float2(*(__half2*)&xv.y);
                    float wt = sc[t];
                    a0 = fmaf(wt, x0.x, a0);
                    a1 = fmaf(wt, x0.y, a1);
                    a2 = fmaf(wt, x1.x, a2);
                    a3 = fmaf(wt, x1.y, a3);
                }
                pack_a(g_cpk, b, u0,     a0, a1);
                pack_a(g_cpk, b, u0 + 2, a2, a3);
            }
        }
        grid_bar();   // bar1: ctx + hr ready

        // ---- phase 4: g_z = ctx @ Wk (128 tiles, one per block) ----
        hgemm_tile(g_cpk, g_Wpk2, (const float*)0, g_z, N2, bid);
        grid_bar();   // bar2: z ready

        // ---- phase 5: LSTM gates + state + projection ----
        {
            const int b2 = bid >> 1, half = bid & 1;
            const int j0 = half * 512 + tid * 2;
            const float* zb = g_z + (size_t)b2 * N2;
            const float* hb = g_q + (size_t)b2 * N1 + 1024;
            float2 a, b;
            a = *(const float2*)&zb[j0];        b = *(const float2*)&hb[j0];
            float2 zi = { bl[j0]   + a.x + b.x, bl[j0+1]   + a.y + b.y };
            a = *(const float2*)&zb[1024+j0];   b = *(const float2*)&hb[1024+j0];
            float2 zf = { bl[1024+j0] + a.x + b.x, bl[1024+j0+1] + a.y + b.y };
            a = *(const float2*)&zb[2048+j0];   b = *(const float2*)&hb[2048+j0];
            float2 zg = { bl[2048+j0] + a.x + b.x, bl[2048+j0+1] + a.y + b.y };
            a = *(const float2*)&zb[3072+j0];   b = *(const float2*)&hb[3072+j0];
            float2 zo = { bl[3072+j0] + a.x + b.x, bl[3072+j0+1] + a.y + b.y };

            float2 cold = *(const float2*)&g_c[b2 * 1024 + j0];
            float cx = sigf(zf.x) * cold.x + sigf(zi.x) * fast_tanh(zg.x);
            float cy = sigf(zf.y) * cold.y + sigf(zi.y) * fast_tanh(zg.y);
            float hx = sigf(zo.x) * fast_tanh(cx);
            float hy = sigf(zo.y) * fast_tanh(cy);
            *(float2*)&g_c[b2 * 1024 + j0] = make_float2(cx, cy);
            pack_a(g_hpk, b2, j0, hx, hy);

            float p = hx * Wo[j0] + hy * Wo[j0 + 1];
            if (tid == 0 && half == 0) p += bo[0];
#pragma unroll
            for (int o = 16; o; o >>= 1) p += __shfl_xor_sync(0xffffffffu, p, o);
            if (!lane) red[warp] = p;
            __syncthreads();
            if (tid == 0) {
                float acc = 0.f;
#pragma unroll
                for (int w2 = 0; w2 < 8; w2++) acc += red[w2];
                atomicAdd(&out[s * 64 + b2], acc);
            }
            __syncthreads();
        }
        grid_bar();   // bar3: h,c ready for next step
    }
}

// ---------------- host launcher ----------------
extern "C" void kernel_launch(void* const* d_in, const int* in_sizes, int n_in,
                              void* d_out, int out_size)
{
    const float* inputs = (const float*)d_in[0];
    const float* We1 = (const float*)d_in[1];  const float* be1 = (const float*)d_in[2];
    const float* We2 = (const float*)d_in[3];  const float* be2 = (const float*)d_in[4];
    const float* W1  = (const float*)d_in[5];  const float* b1  = (const float*)d_in[6];
    const float* W2  = (const float*)d_in[7];  const float* b2k = (const float*)d_in[8];
    const float* V   = (const float*)d_in[9];  /* bV shift-invariant in softmax */
    const float* Wk  = (const float*)d_in[11]; const float* Wr  = (const float*)d_in[12];
    const float* bl  = (const float*)d_in[13]; const float* Wo  = (const float*)d_in[14];
    const float* bo  = (const float*)d_in[15];
    float* out = (float*)d_out;

    void *p_h1pk, *p_xpk, *p_xh, *p_keh, *p_We2pk, *p_W2pk;
    cudaGetSymbolAddress(&p_h1pk,  g_h1pk);
    cudaGetSymbolAddress(&p_xpk,   g_xpk);
    cudaGetSymbolAddress(&p_xh,    g_xh);
    cudaGetSymbolAddress(&p_keh,   g_keh);
    cudaGetSymbolAddress(&p_We2pk, g_We2pk);
    cudaGetSymbolAddress(&p_W2pk,  g_W2pk);

    pack_weights<<<5632, 512>>>(W1, Wr, Wk, We2, W2);
    sgemm128_pack<<<dim3(UU / 128, NROW / 128), 256>>>(inputs, We1, be1, UU, DINN);
    hgemm_big<<<(NROW / 64) * (UU / 32), 256>>>(
        (const __nv_bfloat16*)p_h1pk, (const __nv_bfloat16*)p_We2pk, be2, 1, UU,
        (__nv_bfloat16*)p_xpk, (__half*)p_xh);
    hgemm_big<<<(NROW / 64) * (UU / 32), 256>>>(
        (const __nv_bfloat16*)p_xpk, (const __nv_bfloat16*)p_W2pk, b2k, 0, UU,
        (__nv_bfloat16*)0, (__half*)p_keh);
    init_state<<<64, 1024>>>(out);
    decode_persistent<<<NB, 256>>>(b1, V, bl, Wo, bo, out);
}

// round 9
// speedup vs baseline: 2.3185x; 1.3504x over previous
#include <cuda_runtime.h>
#include <cuda_bf16.h>
#include <cuda_fp16.h>
#include <math.h>

#define BB   64
#define TT   256
#define DINN 128
#define UU   1024
#define SEQ  256
#define NROW (BB*TT)
#define NB   128
#define N1   5120       // [W1 | Wr]
#define N2   4096       // Wk

// ---------------- device scratch ----------------
__device__ __nv_bfloat16 g_h1pk[(size_t)NROW * UU * 2];   // h1 A-frags
__device__ __nv_bfloat16 g_xpk [(size_t)NROW * UU * 2];   // x  A-frags
__device__ __half g_xh [(size_t)NROW * UU];               // x  fp16 linear
__device__ __half g_keh[(size_t)NROW * UU];               // keys fp16 linear
__device__ __nv_bfloat16 g_Wpk1 [(size_t)UU * N1 * 2];    // B-frags [W1|Wr]
__device__ __nv_bfloat16 g_Wpk2 [(size_t)UU * N2 * 2];    // B-frags Wk
__device__ __nv_bfloat16 g_We2pk[(size_t)UU * UU * 2];    // B-frags We2
__device__ __nv_bfloat16 g_W2pk [(size_t)UU * UU * 2];    // B-frags W2
__device__ __nv_bfloat16 g_hpk[BB * UU * 2];              // A-frags h
__device__ __nv_bfloat16 g_cpk[BB * UU * 2];              // A-frags ctx
__device__ float g_qp[2][BB][N1];                         // split-K partials
__device__ float g_zp[2][BB][N2];
__device__ float g_c [BB * UU];
__device__ float g_sc[BB * TT];
__device__ unsigned g_bar_cnt = 0;
__device__ unsigned g_bar_gen = 0;

// ---------------- helpers ----------------
__device__ __forceinline__ float tanh_hw(float x) {
    float y; asm("tanh.approx.f32 %0, %1;" : "=f"(y) : "f"(x)); return y;
}
__device__ __forceinline__ float fast_tanh(float x) {
    float e = __expf(2.0f * x);
    return 1.0f - __fdividef(2.0f, e + 1.0f);
}
__device__ __forceinline__ float sigf(float x) {
    return __fdividef(1.0f, 1.0f + __expf(-x));
}
__device__ __forceinline__ void mma16816(float d[4], const uint4& a, const uint2& b) {
    asm("mma.sync.aligned.m16n8k16.row.col.f32.bf16.bf16.f32 "
        "{%0,%1,%2,%3},{%4,%5,%6,%7},{%8,%9},{%0,%1,%2,%3};"
        : "+f"(d[0]), "+f"(d[1]), "+f"(d[2]), "+f"(d[3])
        : "r"(a.x), "r"(a.y), "r"(a.z), "r"(a.w), "r"(b.x), "r"(b.y));
}
__device__ __forceinline__ void cp16(void* smem, const void* g) {
    unsigned s = (unsigned)__cvta_generic_to_shared(smem);
    asm volatile("cp.async.cg.shared.global [%0], [%1], 16;" :: "r"(s), "l"(g));
}
__device__ __forceinline__ void cp_commit() {
    asm volatile("cp.async.commit_group;");
}
template<int N> __device__ __forceinline__ void cp_wait() {
    asm volatile("cp.async.wait_group %0;" :: "n"(N));
}

// grid barrier: release-arrive / acquire-spin, thread0 only
__device__ __forceinline__ void grid_bar() {
    __syncthreads();
    if (threadIdx.x == 0) {
        unsigned gen;
        asm volatile("ld.acquire.gpu.u32 %0, [%1];" : "=r"(gen) : "l"(&g_bar_gen));
        unsigned prev;
        asm volatile("atom.add.release.gpu.u32 %0, [%1], 1;"
                     : "=r"(prev) : "l"(&g_bar_cnt));
        if (prev == NB - 1) {
            asm volatile("st.relaxed.gpu.u32 [%0], 0;" :: "l"(&g_bar_cnt));
            unsigned d;
            asm volatile("atom.add.release.gpu.u32 %0, [%1], 1;"
                         : "=r"(d) : "l"(&g_bar_gen));
        } else {
            unsigned g;
            do {
                asm volatile("ld.acquire.gpu.u32 %0, [%1];" : "=r"(g) : "l"(&g_bar_gen));
            } while (g == gen);
        }
    }
    __syncthreads();
}

// ---------------- split + A-fragment pack ----------------
__device__ __forceinline__ void split_bf16(float v, __nv_bfloat16& hi, __nv_bfloat16& lo) {
    hi = __float2bfloat16(v);
    lo = __float2bfloat16(v - __bfloat162float(hi));
}
__device__ __forceinline__ void pack_a(__nv_bfloat16* dst, int row, int u,
                                       float vx, float vy)
{
    const int mt = row >> 4, rm = row & 15;
    const int kt = u >> 4,  cm = u & 15;          // u even
    const int lane = (rm & 7) * 4 + ((cm & 7) >> 1);
    const int reg  = (rm >> 3) + ((cm >> 3) & 1) * 2;
    const size_t base = ((size_t)(mt * 64 + kt) * 32 + lane) * 16;
    __nv_bfloat16 hx, lx, hy, ly;
    split_bf16(vx, hx, lx);
    split_bf16(vy, hy, ly);
    __nv_bfloat162 hp; hp.x = hx; hp.y = hy;
    __nv_bfloat162 lp; lp.x = lx; lp.y = ly;
    *(__nv_bfloat162*)&dst[base + reg * 2]     = hp;
    *(__nv_bfloat162*)&dst[base + 8 + reg * 2] = lp;
}

// ---------------- GEMM1 (fp32 SIMT, K=128): h1pk = pack(relu(inputs@We1+be1)) ----
__global__ __launch_bounds__(256, 2)
void sgemm128_pack(const float* __restrict__ A, const float* __restrict__ Bm,
                   const float* __restrict__ bias, int N, int K)
{
    __shared__ float As[8][128];
    __shared__ float Bs[8][128];
    const int tid  = threadIdx.x;
    const int brow = blockIdx.y, bcol = blockIdx.x;
    const int tr = tid >> 4, tc = tid & 15;
    const int aRow = tid >> 1, aCol = (tid & 1) * 4;
    const int bRow = tid >> 5, bCol = (tid & 31) * 4;
    const float* Ap = A + (size_t)(brow * 128) * K;
    const float* Bp = Bm + bcol * 128;

    float acc[8][8];
#pragma unroll
    for (int i = 0; i < 8; i++)
#pragma unroll
        for (int j = 0; j < 8; j++) acc[i][j] = 0.f;

    for (int k0 = 0; k0 < K; k0 += 8) {
        float4 av = *(const float4*)(Ap + (size_t)aRow * K + k0 + aCol);
        As[aCol + 0][aRow] = av.x; As[aCol + 1][aRow] = av.y;
        As[aCol + 2][aRow] = av.z; As[aCol + 3][aRow] = av.w;
        float4 bv = *(const float4*)(Bp + (size_t)(k0 + bRow) * N + bCol);
        *(float4*)&Bs[bRow][bCol] = bv;
        __syncthreads();
#pragma unroll
        for (int kk = 0; kk < 8; kk++) {
            float4 a0 = *(const float4*)&As[kk][tr * 8];
            float4 a1 = *(const float4*)&As[kk][tr * 8 + 4];
            float4 b0 = *(const float4*)&Bs[kk][tc * 8];
            float4 b1 = *(const float4*)&Bs[kk][tc * 8 + 4];
            float ar[8] = {a0.x,a0.y,a0.z,a0.w,a1.x,a1.y,a1.z,a1.w};
            float br[8] = {b0.x,b0.y,b0.z,b0.w,b1.x,b1.y,b1.z,b1.w};
#pragma unroll
            for (int i = 0; i < 8; i++)
#pragma unroll
                for (int j = 0; j < 8; j++)
                    acc[i][j] = fmaf(ar[i], br[j], acc[i][j]);
        }
        __syncthreads();
    }
#pragma unroll
    for (int i = 0; i < 8; i++) {
        int row = brow * 128 + tr * 8 + i;
#pragma unroll
        for (int j = 0; j < 8; j += 2) {
            int col = bcol * 128 + tc * 8 + j;
            float v0 = fmaxf(acc[i][j]     + bias[col],     0.f);
            float v1 = fmaxf(acc[i][j + 1] + bias[col + 1], 0.f);
            pack_a(g_h1pk, row, col, v0, v1);
        }
    }
}

// ---------------- pack weights into split B-fragment layout ----------------
__global__ void pack_weights(const float* __restrict__ W1, const float* __restrict__ Wr,
                             const float* __restrict__ Wk, const float* __restrict__ We2,
                             const float* __restrict__ W2)
{
    const int TOT1 = (N1 / 8) * 64 * 32;
    const int TOT2 = (N2 / 8) * 64 * 32;
    const int TOT3 = (UU / 8) * 64 * 32;
    int c = blockIdx.x * blockDim.x + threadIdx.x;
    const float* W; int ld; __nv_bfloat16* dst; int cl; int nsub = 0;
    if (c < TOT1) {
        cl = c; dst = g_Wpk1;
        int nt = cl / 2048, l = cl & 31;
        int n = nt * 8 + (l >> 2);
        if (n < 1024) { W = W1; ld = 1024; }
        else          { W = Wr; ld = 4096; nsub = 1024; }
    } else if (c < TOT1 + TOT2) {
        cl = c - TOT1; dst = g_Wpk2; W = Wk; ld = 4096;
    } else if (c < TOT1 + TOT2 + TOT3) {
        cl = c - TOT1 - TOT2; dst = g_We2pk; W = We2; ld = 1024;
    } else if (c < TOT1 + TOT2 + 2 * TOT3) {
        cl = c - TOT1 - TOT2 - TOT3; dst = g_W2pk; W = W2; ld = 1024;
    } else return;

    int nt = cl / 2048, rem = cl % 2048, kt = rem >> 5, l = rem & 31;
    int n  = nt * 8 + (l >> 2) - nsub;
    int k0 = kt * 16 + (l & 3) * 2;
    float w[4];
    w[0] = W[(size_t)(k0    ) * ld + n];
    w[1] = W[(size_t)(k0 + 1) * ld + n];
    w[2] = W[(size_t)(k0 + 8) * ld + n];
    w[3] = W[(size_t)(k0 + 9) * ld + n];
    __nv_bfloat16* o = dst + (size_t)cl * 8;
#pragma unroll
    for (int i = 0; i < 4; i++) split_bf16(w[i], o[i], o[4 + i]);
}

// ---------------- big split-bf16 HMMA (precompute) ----------------
__global__ __launch_bounds__(256)
void hgemm_big(const __nv_bfloat16* __restrict__ Apk,
               const __nv_bfloat16* __restrict__ Wpk,
               const float* __restrict__ bias, int doRelu, int N,
               __nv_bfloat16* __restrict__ outPk, __half* __restrict__ outH)
{
    const int tiles_n = N / 32;
    const int tm = blockIdx.x / tiles_n, tn = blockIdx.x % tiles_n;
    const int tid = threadIdx.x;
    const int w = tid >> 5, l = tid & 31;
    const int mt = w >> 1, np = w & 1;
    const int mtg = tm * 4 + mt;
    const uint4* a_it  = (const uint4*)Apk + ((size_t)mtg * 2048 + l) * 2;
    const int nt0 = tn * 4 + np * 2;
    const uint4* b0_it = (const uint4*)Wpk + (size_t)nt0 * 2048 + l;
    const uint4* b1_it = b0_it + 2048;

    float d0[4] = {0.f,0.f,0.f,0.f};
    float d1[4] = {0.f,0.f,0.f,0.f};
#pragma unroll 4
    for (int kt = 0; kt < 64; kt++) {
        uint4 aH = a_it[(size_t)kt * 64];
        uint4 aL = a_it[(size_t)kt * 64 + 1];
        uint4 b0 = b0_it[kt * 32];
        uint4 b1 = b1_it[kt * 32];
        uint2 b0H = make_uint2(b0.x, b0.y), b0L = make_uint2(b0.z, b0.w);
        uint2 b1H = make_uint2(b1.x, b1.y), b1L = make_uint2(b1.z, b1.w);
        mma16816(d0, aH, b0H);
        mma16816(d0, aH, b0L);
        mma16816(d0, aL, b0H);
        mma16816(d1, aH, b1H);
        mma16816(d1, aH, b1L);
        mma16816(d1, aL, b1H);
    }
    const int r0 = tm * 64 + mt * 16 + (l >> 2);
    const int c0 = tn * 32 + np * 16 + ((l & 3) << 1);
    float2 bbA = *(const float2*)&bias[c0];
    float2 bbB = *(const float2*)&bias[c0 + 8];
    d0[0] += bbA.x; d0[1] += bbA.y; d0[2] += bbA.x; d0[3] += bbA.y;
    d1[0] += bbB.x; d1[1] += bbB.y; d1[2] += bbB.x; d1[3] += bbB.y;
    if (doRelu) {
#pragma unroll
        for (int i = 0; i < 4; i++) {
            d0[i] = fmaxf(d0[i], 0.f);
            d1[i] = fmaxf(d1[i], 0.f);
        }
    }
    if (outH) {
        *(__half2*)&outH[(size_t)r0 * N + c0]           = __floats2half2_rn(d0[0], d0[1]);
        *(__half2*)&outH[(size_t)(r0 + 8) * N + c0]     = __floats2half2_rn(d0[2], d0[3]);
        *(__half2*)&outH[(size_t)r0 * N + c0 + 8]       = __floats2half2_rn(d1[0], d1[1]);
        *(__half2*)&outH[(size_t)(r0 + 8) * N + c0 + 8] = __floats2half2_rn(d1[2], d1[3]);
    }
    if (outPk) {
        pack_a(outPk, r0,     c0,     d0[0], d0[1]);
        pack_a(outPk, r0 + 8, c0,     d0[2], d0[3]);
        pack_a(outPk, r0,     c0 + 8, d1[0], d1[1]);
        pack_a(outPk, r0 + 8, c0 + 8, d1[2], d1[3]);
    }
}

// ---------------- init ----------------
__global__ void init_state(float* __restrict__ out)
{
    int idx = blockIdx.x * blockDim.x + threadIdx.x;
    if (idx < BB * UU) {
        g_c[idx] = 0.f;
        g_hpk[idx] = __float2bfloat16(0.f);
        g_hpk[BB * UU + idx] = __float2bfloat16(0.f);
    }
    if (idx < SEQ * BB) out[idx] = 0.f;
    if (idx == 0) g_bar_cnt = 0;
}

// ---------------- smem-staged 64xN step-GEMM task (split-K half) ----------
// task: C[0:64, n0:n0+NT*8] = A[:, kh*512:+512] @ W, k-chunks of 128, cp.async 2-buf
template<int NJ>   // NJ = nt8 per warp (tile N = 16*NJ); NJ=5 -> 80 cols, NJ=4 -> 64
__device__ __forceinline__ void gtile(const uint4* __restrict__ Apk,
                                      const uint4* __restrict__ Wpk,
                                      float* __restrict__ C, int ldc,
                                      int n0, int khalf,
                                      uint4* sA, uint4* sB)
{
    constexpr int NT = 2 * NJ;
    const int tid = threadIdx.x;
    const int w = tid >> 5, l = tid & 31;
    const int mt = w >> 1, np = w & 1;
    const int nt8base = n0 >> 3;
    const int ktbase = khalf * 32;

    float d[NJ][4];
#pragma unroll
    for (int j = 0; j < NJ; j++)
#pragma unroll
        for (int i = 0; i < 4; i++) d[j][i] = 0.f;

    // chunk loader (8 kt = k128)
    auto load = [&](int buf, int cix) {
        const int kt0 = ktbase + cix * 8;
#pragma unroll
        for (int i = tid; i < 1024; i += 256) {
            int lane = i & 31, mtt = (i >> 5) & 3, ktl = i >> 7;
            const uint4* src = Apk + ((size_t)(mtt * 64 + kt0 + ktl) * 32 + lane) * 2;
            cp16(&sA[(((buf * 2 + 0) * 8 + ktl) * 4 + mtt) * 32 + lane], src);
            cp16(&sA[(((buf * 2 + 1) * 8 + ktl) * 4 + mtt) * 32 + lane], src + 1);
        }
        for (int i = tid; i < NT * 8 * 32; i += 256) {
            int lane = i & 31, nt = (i >> 5) % NT, ktl = (i >> 5) / NT;
            const uint4* src = Wpk + (size_t)((nt8base + nt) * 64 + kt0 + ktl) * 32 + lane;
            cp16(&sB[((buf * 8 + ktl) * NT + nt) * 32 + lane], src);
        }
        cp_commit();
    };

    load(0, 0);
    for (int c = 0; c < 4; c++) {
        if (c < 3) { load((c + 1) & 1, c + 1); cp_wait<1>(); }
        else       { cp_wait<0>(); }
        __syncthreads();
        const int buf = c & 1;
#pragma unroll
        for (int ktl = 0; ktl < 8; ktl++) {
            uint4 aH = sA[(((buf * 2 + 0) * 8 + ktl) * 4 + mt) * 32 + l];
            uint4 aL = sA[(((buf * 2 + 1) * 8 + ktl) * 4 + mt) * 32 + l];
#pragma unroll
            for (int j = 0; j < NJ; j++) {
                uint4 b = sB[((buf * 8 + ktl) * NT + np * NJ + j) * 32 + l];
                uint2 bH = make_uint2(b.x, b.y), bL = make_uint2(b.z, b.w);
                mma16816(d[j], aH, bH);
                mma16816(d[j], aH, bL);
                mma16816(d[j], aL, bH);
            }
        }
        __syncthreads();
    }
    const int r0 = mt * 16 + (l >> 2);
#pragma unroll
    for (int j = 0; j < NJ; j++) {
        const int c0 = n0 + (np * NJ + j) * 8 + ((l & 3) << 1);
        *(float2*)&C[(size_t)r0 * ldc + c0]       = make_float2(d[j][0], d[j][1]);
        *(float2*)&C[(size_t)(r0 + 8) * ldc + c0] = make_float2(d[j][2], d[j][3]);
    }
}

// ---------------- persistent decode (uniform phases, 5 bars/step) ----------
extern __shared__ uint4 dynsm[];
__global__ __launch_bounds__(256, 1)
void decode_persistent(const float* __restrict__ b1, const float* __restrict__ V,
                       const float* __restrict__ bl, const float* __restrict__ Wo,
                       const float* __restrict__ bo, float* __restrict__ out)
{
    __shared__ float sm[256];
    __shared__ float red[8];
    uint4* sA = dynsm;          // 4096 uint4 = 64 KB
    uint4* sB = dynsm + 4096;   // up to 5120 uint4 = 80 KB
    const int tid  = threadIdx.x;
    const int bid  = blockIdx.x;
    const int warp = tid >> 5, lane = tid & 31;

    const uint4* hpk_u4  = (const uint4*)g_hpk;
    const uint4* cpk_u4  = (const uint4*)g_cpk;
    const uint4* wpk1_u4 = (const uint4*)g_Wpk1;
    const uint4* wpk2_u4 = (const uint4*)g_Wpk2;

    for (int s = 0; s < SEQ; s++) {
        // ---- phase 1: qp[kh] = h @ [W1|Wr] (64 tiles x 80 cols, split-K2) ----
        {
            const int tile = bid & 63, kh = bid >> 6;
            gtile<5>(hpk_u4, wpk1_u4, &g_qp[kh][0][0], N1, tile * 80, kh, sA, sB);
        }
        grid_bar();

        // ---- phase 2: scores for (b, thalf) ----
        {
            const int b = bid >> 1, thalf = bid & 1;
            float qr[32], vr[32];
#pragma unroll
            for (int it = 0; it < 4; it++) {
                const int base = it * 256 + lane * 8;
#pragma unroll
                for (int k2 = 0; k2 < 8; k2 += 4) {
                    float4 q0 = *(const float4*)&g_qp[0][b][base + k2];
                    float4 q1 = *(const float4*)&g_qp[1][b][base + k2];
                    float4 bb = *(const float4*)&b1[base + k2];
                    float4 vv = *(const float4*)&V[base + k2];
                    qr[it*8+k2+0] = q0.x + q1.x + bb.x;  vr[it*8+k2+0] = vv.x;
                    qr[it*8+k2+1] = q0.y + q1.y + bb.y;  vr[it*8+k2+1] = vv.y;
                    qr[it*8+k2+2] = q0.z + q1.z + bb.z;  vr[it*8+k2+2] = vv.z;
                    qr[it*8+k2+3] = q0.w + q1.w + bb.w;  vr[it*8+k2+3] = vv.w;
                }
            }
            for (int t = warp; t < 128; t += 8) {
                const int tt = thalf * 128 + t;
                const uint4* kp = (const uint4*)(g_keh + ((size_t)(b * 256 + tt)) * 1024);
                float s0 = 0.f;
#pragma unroll
                for (int it = 0; it < 4; it++) {
                    uint4 kv = kp[it * 32 + lane];
                    float2 f0 = __half22float2(*(__half2*)&kv.x);
                    float2 f1 = __half22float2(*(__half2*)&kv.y);
                    float2 f2 = __half22float2(*(__half2*)&kv.z);
                    float2 f3 = __half22float2(*(__half2*)&kv.w);
                    s0 += vr[it*8+0] * tanh_hw(qr[it*8+0] + f0.x);
                    s0 += vr[it*8+1] * tanh_hw(qr[it*8+1] + f0.y);
                    s0 += vr[it*8+2] * tanh_hw(qr[it*8+2] + f1.x);
                    s0 += vr[it*8+3] * tanh_hw(qr[it*8+3] + f1.y);
                    s0 += vr[it*8+4] * tanh_hw(qr[it*8+4] + f2.x);
                    s0 += vr[it*8+5] * tanh_hw(qr[it*8+5] + f2.y);
                    s0 += vr[it*8+6] * tanh_hw(qr[it*8+6] + f3.x);
                    s0 += vr[it*8+7] * tanh_hw(qr[it*8+7] + f3.y);
                }
#pragma unroll
                for (int o = 16; o; o >>= 1) s0 += __shfl_xor_sync(0xffffffffu, s0, o);
                if (!lane) g_sc[b * 256 + tt] = s0;
            }
        }
        grid_bar();

        // ---- phase 3: softmax (redundant) + ctx for (b, uhalf) ----
        {
            const int b = bid >> 1, uhalf = bid & 1;
            float v = g_sc[b * 256 + tid];
            float m = v;
#pragma unroll
            for (int o = 16; o; o >>= 1) m = fmaxf(m, __shfl_xor_sync(0xffffffffu, m, o));
            if (!lane) red[warp] = m;
            __syncthreads();
            float bm = red[0];
#pragma unroll
            for (int w2 = 1; w2 < 8; w2++) bm = fmaxf(bm, red[w2]);
            __syncthreads();
            float e = __expf(v - bm);
            float ss = e;
#pragma unroll
            for (int o = 16; o; o >>= 1) ss += __shfl_xor_sync(0xffffffffu, ss, o);
            if (!lane) red[warp] = ss;
            __syncthreads();
            float bs = 0.f;
#pragma unroll
            for (int w2 = 0; w2 < 8; w2++) bs += red[w2];
            sm[tid] = __fdividef(e, bs);
            __syncthreads();

            const int u0 = uhalf * 512 + tid * 2;
            const __half2* xb = (const __half2*)(g_xh + (size_t)b * 256 * 1024 + u0);
            float ax = 0.f, ay = 0.f;
#pragma unroll 8
            for (int t = 0; t < 256; t++) {
                float2 xv = __half22float2(xb[(size_t)t * 512]);
                float wt = sm[t];
                ax = fmaf(wt, xv.x, ax);
                ay = fmaf(wt, xv.y, ay);
            }
            pack_a(g_cpk, b, u0, ax, ay);
            __syncthreads();
        }
        grid_bar();

        // ---- phase 4: zp[kh] = ctx @ Wk (64 tiles x 64 cols, split-K2) ----
        {
            const int tile = bid & 63, kh = bid >> 6;
            gtile<4>(cpk_u4, wpk2_u4, &g_zp[kh][0][0], N2, tile * 64, kh, sA, sB);
        }
        grid_bar();

        // ---- phase 5: LSTM gates + state + projection for (b2, jhalf) ----
        {
            const int b2 = bid >> 1, jhalf = bid & 1;
            const int j0 = jhalf * 512 + tid * 2;
            const float* z0 = g_zp[0][b2]; const float* z1 = g_zp[1][b2];
            const float* h0 = g_qp[0][b2] + 1024; const float* h1 = g_qp[1][b2] + 1024;
            float2 a0, a1, c0, c1;
            a0 = *(const float2*)&z0[j0];        a1 = *(const float2*)&z1[j0];
            c0 = *(const float2*)&h0[j0];        c1 = *(const float2*)&h1[j0];
            float2 zi = { bl[j0]   + a0.x + a1.x + c0.x + c1.x,
                          bl[j0+1] + a0.y + a1.y + c0.y + c1.y };
            a0 = *(const float2*)&z0[1024+j0];   a1 = *(const float2*)&z1[1024+j0];
            c0 = *(const float2*)&h0[1024+j0];   c1 = *(const float2*)&h1[1024+j0];
            float2 zf = { bl[1024+j0]   + a0.x + a1.x + c0.x + c1.x,
                          bl[1024+j0+1] + a0.y + a1.y + c0.y + c1.y };
            a0 = *(const float2*)&z0[2048+j0];   a1 = *(const float2*)&z1[2048+j0];
            c0 = *(const float2*)&h0[2048+j0];   c1 = *(const float2*)&h1[2048+j0];
            float2 zg = { bl[2048+j0]   + a0.x + a1.x + c0.x + c1.x,
                          bl[2048+j0+1] + a0.y + a1.y + c0.y + c1.y };
            a0 = *(const float2*)&z0[3072+j0];   a1 = *(const float2*)&z1[3072+j0];
            c0 = *(const float2*)&h0[3072+j0];   c1 = *(const float2*)&h1[3072+j0];
            float2 zo = { bl[3072+j0]   + a0.x + a1.x + c0.x + c1.x,
                          bl[3072+j0+1] + a0.y + a1.y + c0.y + c1.y };

            float2 cold = *(const float2*)&g_c[b2 * 1024 + j0];
            float cx = sigf(zf.x) * cold.x + sigf(zi.x) * fast_tanh(zg.x);
            float cy = sigf(zf.y) * cold.y + sigf(zi.y) * fast_tanh(zg.y);
            float hx = sigf(zo.x) * fast_tanh(cx);
            float hy = sigf(zo.y) * fast_tanh(cy);
            *(float2*)&g_c[b2 * 1024 + j0] = make_float2(cx, cy);
            pack_a(g_hpk, b2, j0, hx, hy);

            float p = hx * Wo[j0] + hy * Wo[j0 + 1];
            if (tid == 0 && jhalf == 0) p += bo[0];
#pragma unroll
            for (int o = 16; o; o >>= 1) p += __shfl_xor_sync(0xffffffffu, p, o);
            if (!lane) red[warp] = p;
            __syncthreads();
            if (tid == 0) {
                float acc = 0.f;
#pragma unroll
                for (int w2 = 0; w2 < 8; w2++) acc += red[w2];
                atomicAdd(&out[s * 64 + b2], acc);
            }
            __syncthreads();
        }
        grid_bar();
    }
}

// ---------------- host launcher ----------------
extern "C" void kernel_launch(void* const* d_in, const int* in_sizes, int n_in,
                              void* d_out, int out_size)
{
    const float* inputs = (const float*)d_in[0];
    const float* We1 = (const float*)d_in[1];  const float* be1 = (const float*)d_in[2];
    const float* We2 = (const float*)d_in[3];  const float* be2 = (const float*)d_in[4];
    const float* W1  = (const float*)d_in[5];  const float* b1  = (const float*)d_in[6];
    const float* W2  = (const float*)d_in[7];  const float* b2k = (const float*)d_in[8];
    const float* V   = (const float*)d_in[9];  /* bV shift-invariant in softmax */
    const float* Wk  = (const float*)d_in[11]; const float* Wr  = (const float*)d_in[12];
    const float* bl  = (const float*)d_in[13]; const float* Wo  = (const float*)d_in[14];
    const float* bo  = (const float*)d_in[15];
    float* out = (float*)d_out;

    void *p_h1pk, *p_xpk, *p_xh, *p_keh, *p_We2pk, *p_W2pk;
    cudaGetSymbolAddress(&p_h1pk,  g_h1pk);
    cudaGetSymbolAddress(&p_xpk,   g_xpk);
    cudaGetSymbolAddress(&p_xh,    g_xh);
    cudaGetSymbolAddress(&p_keh,   g_keh);
    cudaGetSymbolAddress(&p_We2pk, g_We2pk);
    cudaGetSymbolAddress(&p_W2pk,  g_W2pk);

    const int DYN_SMEM = (4096 + 5120) * 16;   // 144 KB: sA 64K + sB 80K
    static int attr_set = 0;
    if (!attr_set) {
        cudaFuncSetAttribute(decode_persistent,
                             cudaFuncAttributeMaxDynamicSharedMemorySize, DYN_SMEM);
        attr_set = 1;
    }

    pack_weights<<<5632, 512>>>(W1, Wr, Wk, We2, W2);
    sgemm128_pack<<<dim3(UU / 128, NROW / 128), 256>>>(inputs, We1, be1, UU, DINN);
    hgemm_big<<<(NROW / 64) * (UU / 32), 256>>>(
        (const __nv_bfloat16*)p_h1pk, (const __nv_bfloat16*)p_We2pk, be2, 1, UU,
        (__nv_bfloat16*)p_xpk, (__half*)p_xh);
    hgemm_big<<<(NROW / 64) * (UU / 32), 256>>>(
        (const __nv_bfloat16*)p_xpk, (const __nv_bfloat16*)p_W2pk, b2k, 0, UU,
        (__nv_bfloat16*)0, (__half*)p_keh);
    init_state<<<64, 1024>>>(out);
    decode_persistent<<<NB, 256, DYN_SMEM>>>(b1, V, bl, Wo, bo, out);
}